// round 1
// baseline (speedup 1.0000x reference)
#include <cuda_runtime.h>
#include <math.h>

#define B_SZ   2
#define SEQ    2048
#define DMODEL 1024
#define DINNER 2048
#define DSTATE 16
#define DTRANK 64
#define DCONV  4
#define MROWS  (B_SZ*SEQ)   // 4096
#define XDBL_W 96           // dt_rank + 2*d_state

// ---------------- scratch (alloc-free rule: __device__ globals) ----------------
__device__ float g_xz  [(size_t)MROWS * 2 * DINNER];  // in_proj output [4096,4096]
__device__ float g_xc  [(size_t)MROWS * DINNER];      // conv+silu output
__device__ float g_xdbl[(size_t)MROWS * XDBL_W];      // x_proj output
__device__ float g_dt  [(size_t)MROWS * DINNER];      // softplus(dt)
__device__ float g_y   [(size_t)MROWS * DINNER];      // scan output (gated)

// ---------------- generic fp32 GEMM: C[M,N] = A[M,K] * Bw[N,K]^T ----------------
// 128x128 tile, BK=8, 256 threads, 8x8 per thread.
// EPI: 0 = none, 1 = softplus(v + bias[n])
template<int EPI>
__global__ void __launch_bounds__(256, 2) sgemm_nt(
    const float* __restrict__ A, const float* __restrict__ Bw,
    float* __restrict__ C, const float* __restrict__ bias,
    int M, int N, int K, int lda, int ldb, int ldc)
{
    __shared__ float As[8][128];
    __shared__ float Bs[8][128];

    int tid  = threadIdx.x;
    int row0 = blockIdx.y * 128;
    int col0 = blockIdx.x * 128;
    int tx = tid & 15;          // 0..15 -> output cols tx*8..tx*8+7
    int ty = tid >> 4;          // 0..15 -> output rows ty*8..ty*8+7

    int ldRow = tid >> 1;       // 0..127
    int ldCol = (tid & 1) * 4;  // 0 or 4

    float acc[8][8];
    #pragma unroll
    for (int i = 0; i < 8; i++)
        #pragma unroll
        for (int j = 0; j < 8; j++) acc[i][j] = 0.f;

    const float* Aptr = A + (size_t)(row0 + ldRow) * lda + ldCol;   // M==4096, always in-bounds
    bool bValid = (col0 + ldRow) < N;
    const float* Bptr = Bw + (size_t)(col0 + ldRow) * ldb + ldCol;

    for (int k0 = 0; k0 < K; k0 += 8) {
        float4 av = *(const float4*)(Aptr + k0);
        float4 bv = bValid ? *(const float4*)(Bptr + k0) : make_float4(0.f, 0.f, 0.f, 0.f);

        As[ldCol + 0][ldRow] = av.x;
        As[ldCol + 1][ldRow] = av.y;
        As[ldCol + 2][ldRow] = av.z;
        As[ldCol + 3][ldRow] = av.w;
        Bs[ldCol + 0][ldRow] = bv.x;
        Bs[ldCol + 1][ldRow] = bv.y;
        Bs[ldCol + 2][ldRow] = bv.z;
        Bs[ldCol + 3][ldRow] = bv.w;
        __syncthreads();

        #pragma unroll
        for (int kk = 0; kk < 8; kk++) {
            float a[8], b[8];
            *(float4*)(a)     = *(const float4*)&As[kk][ty * 8];
            *(float4*)(a + 4) = *(const float4*)&As[kk][ty * 8 + 4];
            *(float4*)(b)     = *(const float4*)&Bs[kk][tx * 8];
            *(float4*)(b + 4) = *(const float4*)&Bs[kk][tx * 8 + 4];
            #pragma unroll
            for (int i = 0; i < 8; i++)
                #pragma unroll
                for (int j = 0; j < 8; j++)
                    acc[i][j] = fmaf(a[i], b[j], acc[i][j]);
        }
        __syncthreads();
    }

    #pragma unroll
    for (int i = 0; i < 8; i++) {
        int r = row0 + ty * 8 + i;
        #pragma unroll
        for (int j = 0; j < 8; j++) {
            int c = col0 + tx * 8 + j;
            if (c < N) {
                float v = acc[i][j];
                if (EPI == 1) {
                    v += bias[c];
                    v = (v > 20.f) ? v : log1pf(__expf(v));
                }
                C[(size_t)r * ldc + c] = v;
            }
        }
    }
}

// ---------------- causal depthwise conv (k=4) + SiLU ----------------
__global__ void conv_silu_kernel(const float* __restrict__ conv_w,
                                 const float* __restrict__ conv_b)
{
    int idx = blockIdx.x * blockDim.x + threadIdx.x;   // over MROWS*DINNER
    int d = idx & (DINNER - 1);
    int m = idx >> 11;           // DINNER = 2048
    int l = m & (SEQ - 1);
    int b = m >> 11;             // SEQ = 2048
    float s = conv_b[d];
    #pragma unroll
    for (int j = 0; j < DCONV; j++) {
        int li = l - (DCONV - 1) + j;
        if (li >= 0)
            s = fmaf(conv_w[d * DCONV + j],
                     g_xz[(size_t)(b * SEQ + li) * (2 * DINNER) + d], s);
    }
    g_xc[idx] = s / (1.f + __expf(-s));   // silu
}

// ---------------- selective scan, fused with D*x residual + silu(z) gate ------
// lane layout: 16 lanes = 16 states of one channel; 2 channels per warp.
__global__ void __launch_bounds__(256) scan_kernel(const float* __restrict__ A_log,
                                                   const float* __restrict__ Dp)
{
    int tid  = threadIdx.x;
    int lane = tid & 31;
    int warp = tid >> 5;
    int ch = blockIdx.x * 16 + warp * 2 + (lane >> 4);   // 0..4095
    int n  = lane & 15;
    int b  = ch >> 11;            // DINNER = 2048
    int d  = ch & (DINNER - 1);

    float Ac = -__expf(A_log[d * DSTATE + n]);
    float Dd = Dp[d];
    float h  = 0.f;

    const float* dt_p = g_dt   + (size_t)b * SEQ * DINNER + d;
    const float* xc_p = g_xc   + (size_t)b * SEQ * DINNER + d;
    const float* z_p  = g_xz   + (size_t)b * SEQ * (2 * DINNER) + DINNER + d;
    const float* bc_p = g_xdbl + (size_t)b * SEQ * XDBL_W + DTRANK + n;
    float*       y_p  = g_y    + (size_t)b * SEQ * DINNER + d;

    for (int t = 0; t < SEQ; t++) {
        float dtv = dt_p[(size_t)t * DINNER];
        float xv  = xc_p[(size_t)t * DINNER];
        float Bn  = bc_p[(size_t)t * XDBL_W];
        float Cn  = bc_p[(size_t)t * XDBL_W + DSTATE];

        float dA = __expf(dtv * Ac);
        h = fmaf(dA, h, dtv * Bn * xv);

        float p = h * Cn;
        p += __shfl_xor_sync(0xffffffffu, p, 8);
        p += __shfl_xor_sync(0xffffffffu, p, 4);
        p += __shfl_xor_sync(0xffffffffu, p, 2);
        p += __shfl_xor_sync(0xffffffffu, p, 1);

        if (n == 0) {
            float zv = z_p[(size_t)t * (2 * DINNER)];
            float yv = fmaf(Dd, xv, p);
            yv *= zv / (1.f + __expf(-zv));
            y_p[(size_t)t * DINNER] = yv;
        }
    }
}

// ---------------- launch ----------------
extern "C" void kernel_launch(void* const* d_in, const int* in_sizes, int n_in,
                              void* d_out, int out_size)
{
    const float* x          = (const float*)d_in[0];
    const float* in_proj_w  = (const float*)d_in[1];
    const float* conv_w     = (const float*)d_in[2];
    const float* conv_b     = (const float*)d_in[3];
    const float* A_log      = (const float*)d_in[4];
    const float* Dp         = (const float*)d_in[5];
    const float* x_proj_w   = (const float*)d_in[6];
    const float* dt_proj_w  = (const float*)d_in[7];
    const float* dt_proj_b  = (const float*)d_in[8];
    const float* out_proj_w = (const float*)d_in[9];
    float*       out        = (float*)d_out;

    float *xz, *xc, *xdbl, *dt, *y;
    cudaGetSymbolAddress((void**)&xz,   g_xz);
    cudaGetSymbolAddress((void**)&xc,   g_xc);
    cudaGetSymbolAddress((void**)&xdbl, g_xdbl);
    cudaGetSymbolAddress((void**)&dt,   g_dt);
    cudaGetSymbolAddress((void**)&y,    g_y);

    // 1) xz = x @ in_proj_w^T          [4096, 4096], K=1024
    sgemm_nt<0><<<dim3(32, 32), 256>>>(x, in_proj_w, xz, nullptr,
                                       MROWS, 2 * DINNER, DMODEL,
                                       DMODEL, DMODEL, 2 * DINNER);

    // 2) causal depthwise conv + silu  -> g_xc
    conv_silu_kernel<<<(MROWS * DINNER) / 256, 256>>>(conv_w, conv_b);

    // 3) x_dbl = xc @ x_proj_w^T       [4096, 96], K=2048
    sgemm_nt<0><<<dim3(1, 32), 256>>>(xc, x_proj_w, xdbl, nullptr,
                                      MROWS, XDBL_W, DINNER,
                                      DINNER, DINNER, XDBL_W);

    // 4) dt = softplus(x_dbl[:, :64] @ dt_proj_w^T + b)   [4096, 2048], K=64
    sgemm_nt<1><<<dim3(16, 32), 256>>>(xdbl, dt_proj_w, dt, dt_proj_b,
                                       MROWS, DINNER, DTRANK,
                                       XDBL_W, DTRANK, DINNER);

    // 5) selective scan + D*x + silu(z) gate  -> g_y
    scan_kernel<<<256, 256>>>(A_log, Dp);

    // 6) out = y @ out_proj_w^T        [4096, 1024], K=2048
    sgemm_nt<0><<<dim3(8, 32), 256>>>(y, out_proj_w, out, nullptr,
                                      MROWS, DMODEL, DINNER,
                                      DINNER, DINNER, DMODEL);
}

// round 3
// speedup vs baseline: 1.0192x; 1.0192x over previous
#include <cuda_runtime.h>
#include <cuda_bf16.h>
#include <math.h>
#include <stdint.h>

#define B_SZ   2
#define SEQ    2048
#define DMODEL 1024
#define DINNER 2048
#define DSTATE 16
#define DTRANK 64
#define DCONV  4
#define MROWS  (B_SZ*SEQ)   // 4096
#define XDBL_W 96           // dt_rank + 2*d_state
#define KSPLIT 4

// ---------------- scratch (alloc-free rule: __device__ globals) ----------------
__device__ float g_xz   [(size_t)MROWS * 2 * DINNER];
__device__ float g_xc   [(size_t)MROWS * DINNER];
__device__ float g_xdbl [(size_t)MROWS * XDBL_W];
__device__ float g_xdblp[(size_t)KSPLIT * MROWS * XDBL_W];
__device__ float g_dt   [(size_t)MROWS * DINNER];

// bf16 hi/lo splits for tensor-core GEMMs
__device__ __nv_bfloat16 g_xh [(size_t)MROWS * DMODEL];
__device__ __nv_bfloat16 g_xl [(size_t)MROWS * DMODEL];
__device__ __nv_bfloat16 g_wih[(size_t)(2*DINNER) * DMODEL];
__device__ __nv_bfloat16 g_wil[(size_t)(2*DINNER) * DMODEL];
__device__ __nv_bfloat16 g_yh [(size_t)MROWS * DINNER];
__device__ __nv_bfloat16 g_yl [(size_t)MROWS * DINNER];
__device__ __nv_bfloat16 g_woh[(size_t)DMODEL * DINNER];
__device__ __nv_bfloat16 g_wol[(size_t)DMODEL * DINNER];

// ======================= helpers =======================
__device__ __forceinline__ uint32_t smem_to_u32(const void* p) {
    uint32_t a;
    asm("{ .reg .u64 t; cvta.to.shared.u64 t, %1; cvt.u32.u64 %0, t; }"
        : "=r"(a) : "l"(p));
    return a;
}

#define LDM_X4(r, addr) \
    asm volatile("ldmatrix.sync.aligned.m8n8.x4.shared.b16 {%0,%1,%2,%3}, [%4];" \
        : "=r"((r)[0]), "=r"((r)[1]), "=r"((r)[2]), "=r"((r)[3]) : "r"(addr))

#define MMA16816(c, a, b0, b1) \
    asm volatile("mma.sync.aligned.m16n8k16.row.col.f32.bf16.bf16.f32 " \
        "{%0,%1,%2,%3}, {%4,%5,%6,%7}, {%8,%9}, {%0,%1,%2,%3};" \
        : "+f"((c)[0]), "+f"((c)[1]), "+f"((c)[2]), "+f"((c)[3]) \
        : "r"((a)[0]), "r"((a)[1]), "r"((a)[2]), "r"((a)[3]), "r"(b0), "r"(b1))

#define CP_ASYNC16(saddr, gptr) \
    asm volatile("cp.async.cg.shared.global [%0], [%1], 16;" \
        :: "r"(saddr), "l"(gptr) : "memory")
#define CP_COMMIT() asm volatile("cp.async.commit_group;" ::: "memory")
#define CP_WAIT(n)  asm volatile("cp.async.wait_group %0;" :: "n"(n) : "memory")

// ================= split-bf16 HMMA GEMM: C[M,N] = A[M,K] @ B[N,K]^T =================
// 128x128 tile, BK=32, 256 threads, warp tile 64x32, cp.async double buffer.
#define LDSH   40                    // padded stride in halves (32 + 8)
#define STG_H  (128*LDSH)            // halves per array per stage (5120)
#define STAGE_H (4*STG_H)            // Ah,Al,Bh,Bl
#define HMMA_SMEM (2*STAGE_H*2)      // bytes = 81920

__global__ void __launch_bounds__(256, 1)
hmma_gemm(const __nv_bfloat16* __restrict__ Ah, const __nv_bfloat16* __restrict__ Al,
          const __nv_bfloat16* __restrict__ Bh, const __nv_bfloat16* __restrict__ Bl,
          float* __restrict__ C, int K, int N)
{
    extern __shared__ __nv_bfloat16 sm[];
    const int tid  = threadIdx.x;
    const int lane = tid & 31;
    const int w    = tid >> 5;
    const int wm   = w >> 2;          // 0..1
    const int wn   = w & 3;           // 0..3
    const int row0 = blockIdx.y * 128;
    const int col0 = blockIdx.x * 128;
    const uint32_t sbase = smem_to_u32(sm);

    const int nc = K >> 5;            // chunks of 32

    // async load of chunk c into stage s
    auto load_stage = [&](int c, int s) {
        #pragma unroll
        for (int j = 0; j < 2; j++) {
            int i = tid + j * 256;          // 0..511
            int r = i >> 2, q = i & 3;      // row 0..127, 16B seg 0..3
            size_t gA = (size_t)(row0 + r) * K + c * 32 + q * 8;
            size_t gB = (size_t)(col0 + r) * K + c * 32 + q * 8;
            uint32_t so = (uint32_t)(s * STAGE_H + r * LDSH + q * 8);   // halves
            uint32_t sa = sbase + so * 2;
            CP_ASYNC16(sa,                (const void*)(Ah + gA));
            CP_ASYNC16(sa + STG_H*2,      (const void*)(Al + gA));
            CP_ASYNC16(sa + 2*STG_H*2,    (const void*)(Bh + gB));
            CP_ASYNC16(sa + 3*STG_H*2,    (const void*)(Bl + gB));
        }
    };

    float acc[4][4][4];
    #pragma unroll
    for (int mi = 0; mi < 4; mi++)
        #pragma unroll
        for (int nj = 0; nj < 4; nj++)
            #pragma unroll
            for (int q = 0; q < 4; q++) acc[mi][nj][q] = 0.f;

    load_stage(0, 0);
    CP_COMMIT();

    for (int c = 0; c < nc; c++) {
        int s = c & 1;
        if (c + 1 < nc) {
            load_stage(c + 1, (c + 1) & 1);
            CP_COMMIT();
            CP_WAIT(1);
        } else {
            CP_WAIT(0);
        }
        __syncthreads();

        #pragma unroll
        for (int ks = 0; ks < 2; ks++) {
            uint32_t ah[4][4], al[4][4];
            #pragma unroll
            for (int mi = 0; mi < 4; mi++) {
                uint32_t off = (uint32_t)(s * STAGE_H
                             + (wm*64 + mi*16 + (lane & 15)) * LDSH
                             + ks*16 + (lane >> 4) * 8);
                uint32_t ad = sbase + off * 2;
                LDM_X4(ah[mi], ad);
                LDM_X4(al[mi], ad + STG_H*2);
            }
            uint32_t bh[2][4], bl[2][4];
            #pragma unroll
            for (int np = 0; np < 2; np++) {
                uint32_t off = (uint32_t)(s * STAGE_H + 2*STG_H
                             + (wn*32 + np*16 + (lane & 7) + ((lane >> 3) & 1) * 8) * LDSH
                             + ks*16 + (lane >> 4) * 8);
                uint32_t bd = sbase + off * 2;
                LDM_X4(bh[np], bd);
                LDM_X4(bl[np], bd + STG_H*2);
            }
            #pragma unroll
            for (int mi = 0; mi < 4; mi++)
                #pragma unroll
                for (int np = 0; np < 2; np++)
                    #pragma unroll
                    for (int sub = 0; sub < 2; sub++) {
                        int nj = np * 2 + sub;
                        MMA16816(acc[mi][nj], ah[mi], bh[np][sub], bh[np][sub + 2]);
                        MMA16816(acc[mi][nj], ah[mi], bl[np][sub], bl[np][sub + 2]);
                        MMA16816(acc[mi][nj], al[mi], bh[np][sub], bh[np][sub + 2]);
                    }
        }
        __syncthreads();   // compute done before next prefetch overwrites this stage
    }

    // epilogue: fragment layout d0,d1 -> (m, n..n+1); d2,d3 -> (m+8, n..n+1)
    #pragma unroll
    for (int mi = 0; mi < 4; mi++)
        #pragma unroll
        for (int nj = 0; nj < 4; nj++) {
            int r = row0 + wm*64 + mi*16 + (lane >> 2);
            int cc = col0 + wn*32 + nj*8 + (lane & 3) * 2;
            *(float2*)(C + (size_t)r * N + cc) =
                make_float2(acc[mi][nj][0], acc[mi][nj][1]);
            *(float2*)(C + (size_t)(r + 8) * N + cc) =
                make_float2(acc[mi][nj][2], acc[mi][nj][3]);
        }
}

// ---------------- fp32 -> bf16 hi/lo split ----------------
__global__ void split_kernel(const float* __restrict__ src,
                             __nv_bfloat16* __restrict__ hi,
                             __nv_bfloat16* __restrict__ lo, int n)
{
    int i = blockIdx.x * blockDim.x + threadIdx.x;
    if (i < n) {
        float v = src[i];
        __nv_bfloat16 h = __float2bfloat16(v);
        hi[i] = h;
        lo[i] = __float2bfloat16(v - __bfloat162float(h));
    }
}

// ---------------- SIMT fp32 GEMM (dt proj): softplus epilogue -------------
__global__ void __launch_bounds__(256, 2) sgemm_softplus(
    const float* __restrict__ A, const float* __restrict__ Bw,
    float* __restrict__ C, const float* __restrict__ bias,
    int M, int N, int K, int lda, int ldb, int ldc)
{
    __shared__ float As[8][128];
    __shared__ float Bs[8][128];
    int tid  = threadIdx.x;
    int row0 = blockIdx.y * 128;
    int col0 = blockIdx.x * 128;
    int tx = tid & 15, ty = tid >> 4;
    int ldRow = tid >> 1, ldCol = (tid & 1) * 4;

    float acc[8][8];
    #pragma unroll
    for (int i = 0; i < 8; i++)
        #pragma unroll
        for (int j = 0; j < 8; j++) acc[i][j] = 0.f;

    const float* Aptr = A + (size_t)(row0 + ldRow) * lda + ldCol;
    bool bValid = (col0 + ldRow) < N;
    const float* Bptr = Bw + (size_t)(col0 + ldRow) * ldb + ldCol;

    for (int k0 = 0; k0 < K; k0 += 8) {
        float4 av = *(const float4*)(Aptr + k0);
        float4 bv = bValid ? *(const float4*)(Bptr + k0) : make_float4(0.f,0.f,0.f,0.f);
        As[ldCol+0][ldRow] = av.x; As[ldCol+1][ldRow] = av.y;
        As[ldCol+2][ldRow] = av.z; As[ldCol+3][ldRow] = av.w;
        Bs[ldCol+0][ldRow] = bv.x; Bs[ldCol+1][ldRow] = bv.y;
        Bs[ldCol+2][ldRow] = bv.z; Bs[ldCol+3][ldRow] = bv.w;
        __syncthreads();
        #pragma unroll
        for (int kk = 0; kk < 8; kk++) {
            float a[8], b[8];
            *(float4*)(a)     = *(const float4*)&As[kk][ty*8];
            *(float4*)(a + 4) = *(const float4*)&As[kk][ty*8+4];
            *(float4*)(b)     = *(const float4*)&Bs[kk][tx*8];
            *(float4*)(b + 4) = *(const float4*)&Bs[kk][tx*8+4];
            #pragma unroll
            for (int i = 0; i < 8; i++)
                #pragma unroll
                for (int j = 0; j < 8; j++)
                    acc[i][j] = fmaf(a[i], b[j], acc[i][j]);
        }
        __syncthreads();
    }
    #pragma unroll
    for (int i = 0; i < 8; i++) {
        int r = row0 + ty*8 + i;
        #pragma unroll
        for (int j = 0; j < 8; j++) {
            int c = col0 + tx*8 + j;
            if (c < N) {
                float v = acc[i][j] + bias[c];
                v = (v > 20.f) ? v : log1pf(__expf(v));
                C[(size_t)r * ldc + c] = v;
            }
        }
    }
}

// ---------------- split-K SIMT GEMM for x_proj (partials, no atomics) ------
__global__ void __launch_bounds__(256, 2) sgemm_splitk(
    const float* __restrict__ A, const float* __restrict__ Bw,
    float* __restrict__ Cpart, int M, int N, int Kc, int lda, int ldb)
{
    __shared__ float As[8][128];
    __shared__ float Bs[8][128];
    int tid  = threadIdx.x;
    int row0 = blockIdx.y * 128;
    int col0 = blockIdx.x * 128;
    int z    = blockIdx.z;
    int tx = tid & 15, ty = tid >> 4;
    int ldRow = tid >> 1, ldCol = (tid & 1) * 4;

    float acc[8][8];
    #pragma unroll
    for (int i = 0; i < 8; i++)
        #pragma unroll
        for (int j = 0; j < 8; j++) acc[i][j] = 0.f;

    const float* Aptr = A + (size_t)(row0 + ldRow) * lda + z * Kc + ldCol;
    bool bValid = (col0 + ldRow) < N;
    const float* Bptr = Bw + (size_t)(col0 + ldRow) * ldb + z * Kc + ldCol;

    for (int k0 = 0; k0 < Kc; k0 += 8) {
        float4 av = *(const float4*)(Aptr + k0);
        float4 bv = bValid ? *(const float4*)(Bptr + k0) : make_float4(0.f,0.f,0.f,0.f);
        As[ldCol+0][ldRow] = av.x; As[ldCol+1][ldRow] = av.y;
        As[ldCol+2][ldRow] = av.z; As[ldCol+3][ldRow] = av.w;
        Bs[ldCol+0][ldRow] = bv.x; Bs[ldCol+1][ldRow] = bv.y;
        Bs[ldCol+2][ldRow] = bv.z; Bs[ldCol+3][ldRow] = bv.w;
        __syncthreads();
        #pragma unroll
        for (int kk = 0; kk < 8; kk++) {
            float a[8], b[8];
            *(float4*)(a)     = *(const float4*)&As[kk][ty*8];
            *(float4*)(a + 4) = *(const float4*)&As[kk][ty*8+4];
            *(float4*)(b)     = *(const float4*)&Bs[kk][tx*8];
            *(float4*)(b + 4) = *(const float4*)&Bs[kk][tx*8+4];
            #pragma unroll
            for (int i = 0; i < 8; i++)
                #pragma unroll
                for (int j = 0; j < 8; j++)
                    acc[i][j] = fmaf(a[i], b[j], acc[i][j]);
        }
        __syncthreads();
    }
    float* Cz = Cpart + (size_t)z * M * N;
    #pragma unroll
    for (int i = 0; i < 8; i++) {
        int r = row0 + ty*8 + i;
        #pragma unroll
        for (int j = 0; j < 8; j++) {
            int c = col0 + tx*8 + j;
            if (c < N) Cz[(size_t)r * N + c] = acc[i][j];
        }
    }
}

__global__ void reduce_splitk(float* __restrict__ dst, const float* __restrict__ parts, int n)
{
    int i = blockIdx.x * blockDim.x + threadIdx.x;
    if (i < n)
        dst[i] = parts[i] + parts[i + (size_t)n] + parts[i + 2*(size_t)n] + parts[i + 3*(size_t)n];
}

// ---------------- causal depthwise conv (k=4) + SiLU ----------------
__global__ void conv_silu_kernel(const float* __restrict__ conv_w,
                                 const float* __restrict__ conv_b)
{
    int idx = blockIdx.x * blockDim.x + threadIdx.x;
    int d = idx & (DINNER - 1);
    int m = idx >> 11;
    int l = m & (SEQ - 1);
    int b = m >> 11;
    float s = conv_b[d];
    #pragma unroll
    for (int j = 0; j < DCONV; j++) {
        int li = l - (DCONV - 1) + j;
        if (li >= 0)
            s = fmaf(conv_w[d * DCONV + j],
                     g_xz[(size_t)(b * SEQ + li) * (2 * DINNER) + d], s);
    }
    g_xc[idx] = s / (1.f + __expf(-s));
}

// ---------------- selective scan + D*x + silu(z), writes bf16 hi/lo ------
__global__ void __launch_bounds__(256) scan_kernel(const float* __restrict__ A_log,
                                                   const float* __restrict__ Dp)
{
    int tid  = threadIdx.x;
    int lane = tid & 31;
    int warp = tid >> 5;
    int ch = blockIdx.x * 16 + warp * 2 + (lane >> 4);
    int n  = lane & 15;
    int b  = ch >> 11;
    int d  = ch & (DINNER - 1);

    float Ac = -__expf(A_log[d * DSTATE + n]);
    float Dd = Dp[d];
    float h  = 0.f;

    const float* dt_p = g_dt   + (size_t)b * SEQ * DINNER + d;
    const float* xc_p = g_xc   + (size_t)b * SEQ * DINNER + d;
    const float* z_p  = g_xz   + (size_t)b * SEQ * (2 * DINNER) + DINNER + d;
    const float* bc_p = g_xdbl + (size_t)b * SEQ * XDBL_W + DTRANK + n;
    size_t ybase = (size_t)b * SEQ * DINNER + d;

    for (int t = 0; t < SEQ; t++) {
        float dtv = dt_p[(size_t)t * DINNER];
        float xv  = xc_p[(size_t)t * DINNER];
        float Bn  = bc_p[(size_t)t * XDBL_W];
        float Cn  = bc_p[(size_t)t * XDBL_W + DSTATE];

        float dA = __expf(dtv * Ac);
        h = fmaf(dA, h, dtv * Bn * xv);

        float p = h * Cn;
        p += __shfl_xor_sync(0xffffffffu, p, 8);
        p += __shfl_xor_sync(0xffffffffu, p, 4);
        p += __shfl_xor_sync(0xffffffffu, p, 2);
        p += __shfl_xor_sync(0xffffffffu, p, 1);

        if (n == 0) {
            float zv = z_p[(size_t)t * (2 * DINNER)];
            float yv = fmaf(Dd, xv, p);
            yv *= zv / (1.f + __expf(-zv));
            __nv_bfloat16 hh = __float2bfloat16(yv);
            g_yh[ybase + (size_t)t * DINNER] = hh;
            g_yl[ybase + (size_t)t * DINNER] =
                __float2bfloat16(yv - __bfloat162float(hh));
        }
    }
}

// ---------------- launch ----------------
extern "C" void kernel_launch(void* const* d_in, const int* in_sizes, int n_in,
                              void* d_out, int out_size)
{
    const float* x          = (const float*)d_in[0];
    const float* in_proj_w  = (const float*)d_in[1];
    const float* conv_w     = (const float*)d_in[2];
    const float* conv_b     = (const float*)d_in[3];
    const float* A_log      = (const float*)d_in[4];
    const float* Dp         = (const float*)d_in[5];
    const float* x_proj_w   = (const float*)d_in[6];
    const float* dt_proj_w  = (const float*)d_in[7];
    const float* dt_proj_b  = (const float*)d_in[8];
    const float* out_proj_w = (const float*)d_in[9];
    float*       out        = (float*)d_out;

    float *xz, *xc, *xdbl, *xdblp, *dt;
    __nv_bfloat16 *xh, *xl, *wih, *wil, *yh, *yl, *woh, *wol;
    cudaGetSymbolAddress((void**)&xz,    g_xz);
    cudaGetSymbolAddress((void**)&xc,    g_xc);
    cudaGetSymbolAddress((void**)&xdbl,  g_xdbl);
    cudaGetSymbolAddress((void**)&xdblp, g_xdblp);
    cudaGetSymbolAddress((void**)&dt,    g_dt);
    cudaGetSymbolAddress((void**)&xh,  g_xh);
    cudaGetSymbolAddress((void**)&xl,  g_xl);
    cudaGetSymbolAddress((void**)&wih, g_wih);
    cudaGetSymbolAddress((void**)&wil, g_wil);
    cudaGetSymbolAddress((void**)&yh,  g_yh);
    cudaGetSymbolAddress((void**)&yl,  g_yl);
    cudaGetSymbolAddress((void**)&woh, g_woh);
    cudaGetSymbolAddress((void**)&wol, g_wol);

    cudaFuncSetAttribute(hmma_gemm, cudaFuncAttributeMaxDynamicSharedMemorySize,
                         HMMA_SMEM);

    // 0) bf16 hi/lo splits
    split_kernel<<<(MROWS*DMODEL + 255)/256, 256>>>(x, xh, xl, MROWS*DMODEL);
    split_kernel<<<(2*DINNER*DMODEL + 255)/256, 256>>>(in_proj_w, wih, wil, 2*DINNER*DMODEL);
    split_kernel<<<(DMODEL*DINNER + 255)/256, 256>>>(out_proj_w, woh, wol, DMODEL*DINNER);

    // 1) xz = x @ in_proj_w^T  [4096, 4096], K=1024 — HMMA split-bf16
    hmma_gemm<<<dim3(32, 32), 256, HMMA_SMEM>>>(xh, xl, wih, wil, xz, DMODEL, 2*DINNER);

    // 2) causal depthwise conv + silu  -> g_xc
    conv_silu_kernel<<<(MROWS * DINNER) / 256, 256>>>(conv_w, conv_b);

    // 3) x_dbl = xc @ x_proj_w^T  [4096, 96], K=2048 — split-K x4 + reduce
    sgemm_splitk<<<dim3(1, 32, KSPLIT), 256>>>(xc, x_proj_w, xdblp,
                                               MROWS, XDBL_W, DINNER/KSPLIT,
                                               DINNER, DINNER);
    reduce_splitk<<<(MROWS*XDBL_W + 255)/256, 256>>>(xdbl, xdblp, MROWS*XDBL_W);

    // 4) dt = softplus(x_dbl[:, :64] @ dt_proj_w^T + b)   [4096, 2048], K=64
    sgemm_softplus<<<dim3(16, 32), 256>>>(xdbl, dt_proj_w, dt, dt_proj_b,
                                          MROWS, DINNER, DTRANK,
                                          XDBL_W, DTRANK, DINNER);

    // 5) selective scan + D*x + silu(z) gate  -> g_yh/g_yl
    scan_kernel<<<256, 256>>>(A_log, Dp);

    // 6) out = y @ out_proj_w^T  [4096, 1024], K=2048 — HMMA split-bf16
    hmma_gemm<<<dim3(8, 32), 256, HMMA_SMEM>>>(yh, yl, woh, wol, out, DINNER, DMODEL);
}

// round 4
// speedup vs baseline: 2.8643x; 2.8102x over previous
#include <cuda_runtime.h>
#include <cuda_bf16.h>
#include <math.h>
#include <stdint.h>

#define B_SZ   2
#define SEQ    2048
#define DMODEL 1024
#define DINNER 2048
#define DSTATE 16
#define DTRANK 64
#define DCONV  4
#define MROWS  (B_SZ*SEQ)   // 4096
#define XDBL_W 96           // dt_rank + 2*d_state
#define KSPLIT 4

// ---------------- scratch (alloc-free rule: __device__ globals) ----------------
__device__ float g_xz   [(size_t)MROWS * 2 * DINNER];
__device__ float g_xc   [(size_t)MROWS * DINNER];
__device__ float g_xdbl [(size_t)MROWS * XDBL_W];
__device__ float g_xdblp[(size_t)KSPLIT * MROWS * XDBL_W];
__device__ float g_dt   [(size_t)MROWS * DINNER];

// bf16 hi/lo splits for tensor-core GEMMs
__device__ __nv_bfloat16 g_xh [(size_t)MROWS * DMODEL];
__device__ __nv_bfloat16 g_xl [(size_t)MROWS * DMODEL];
__device__ __nv_bfloat16 g_wih[(size_t)(2*DINNER) * DMODEL];
__device__ __nv_bfloat16 g_wil[(size_t)(2*DINNER) * DMODEL];
__device__ __nv_bfloat16 g_yh [(size_t)MROWS * DINNER];
__device__ __nv_bfloat16 g_yl [(size_t)MROWS * DINNER];
__device__ __nv_bfloat16 g_woh[(size_t)DMODEL * DINNER];
__device__ __nv_bfloat16 g_wol[(size_t)DMODEL * DINNER];

// ======================= helpers =======================
__device__ __forceinline__ uint32_t smem_to_u32(const void* p) {
    uint32_t a;
    asm("{ .reg .u64 t; cvta.to.shared.u64 t, %1; cvt.u32.u64 %0, t; }"
        : "=r"(a) : "l"(p));
    return a;
}

#define LDM_X4(r, addr) \
    asm volatile("ldmatrix.sync.aligned.m8n8.x4.shared.b16 {%0,%1,%2,%3}, [%4];" \
        : "=r"((r)[0]), "=r"((r)[1]), "=r"((r)[2]), "=r"((r)[3]) : "r"(addr))

#define MMA16816(c, a, b0, b1) \
    asm volatile("mma.sync.aligned.m16n8k16.row.col.f32.bf16.bf16.f32 " \
        "{%0,%1,%2,%3}, {%4,%5,%6,%7}, {%8,%9}, {%0,%1,%2,%3};" \
        : "+f"((c)[0]), "+f"((c)[1]), "+f"((c)[2]), "+f"((c)[3]) \
        : "r"((a)[0]), "r"((a)[1]), "r"((a)[2]), "r"((a)[3]), "r"(b0), "r"(b1))

#define CP_ASYNC16(saddr, gptr) \
    asm volatile("cp.async.cg.shared.global [%0], [%1], 16;" \
        :: "r"(saddr), "l"(gptr) : "memory")
#define CP_COMMIT() asm volatile("cp.async.commit_group;" ::: "memory")
#define CP_WAIT(n)  asm volatile("cp.async.wait_group %0;" :: "n"(n) : "memory")

// ================= split-bf16 HMMA GEMM: C[M,N] = A[M,K] @ B[N,K]^T =================
#define LDSH   40
#define STG_H  (128*LDSH)
#define STAGE_H (4*STG_H)
#define HMMA_SMEM (2*STAGE_H*2)

__global__ void __launch_bounds__(256, 1)
hmma_gemm(const __nv_bfloat16* __restrict__ Ah, const __nv_bfloat16* __restrict__ Al,
          const __nv_bfloat16* __restrict__ Bh, const __nv_bfloat16* __restrict__ Bl,
          float* __restrict__ C, int K, int N)
{
    extern __shared__ __nv_bfloat16 sm[];
    const int tid  = threadIdx.x;
    const int lane = tid & 31;
    const int w    = tid >> 5;
    const int wm   = w >> 2;
    const int wn   = w & 3;
    const int row0 = blockIdx.y * 128;
    const int col0 = blockIdx.x * 128;
    const uint32_t sbase = smem_to_u32(sm);

    const int nc = K >> 5;

    auto load_stage = [&](int c, int s) {
        #pragma unroll
        for (int j = 0; j < 2; j++) {
            int i = tid + j * 256;
            int r = i >> 2, q = i & 3;
            size_t gA = (size_t)(row0 + r) * K + c * 32 + q * 8;
            size_t gB = (size_t)(col0 + r) * K + c * 32 + q * 8;
            uint32_t so = (uint32_t)(s * STAGE_H + r * LDSH + q * 8);
            uint32_t sa = sbase + so * 2;
            CP_ASYNC16(sa,                (const void*)(Ah + gA));
            CP_ASYNC16(sa + STG_H*2,      (const void*)(Al + gA));
            CP_ASYNC16(sa + 2*STG_H*2,    (const void*)(Bh + gB));
            CP_ASYNC16(sa + 3*STG_H*2,    (const void*)(Bl + gB));
        }
    };

    float acc[4][4][4];
    #pragma unroll
    for (int mi = 0; mi < 4; mi++)
        #pragma unroll
        for (int nj = 0; nj < 4; nj++)
            #pragma unroll
            for (int q = 0; q < 4; q++) acc[mi][nj][q] = 0.f;

    load_stage(0, 0);
    CP_COMMIT();

    for (int c = 0; c < nc; c++) {
        int s = c & 1;
        if (c + 1 < nc) {
            load_stage(c + 1, (c + 1) & 1);
            CP_COMMIT();
            CP_WAIT(1);
        } else {
            CP_WAIT(0);
        }
        __syncthreads();

        #pragma unroll
        for (int ks = 0; ks < 2; ks++) {
            uint32_t ah[4][4], al[4][4];
            #pragma unroll
            for (int mi = 0; mi < 4; mi++) {
                uint32_t off = (uint32_t)(s * STAGE_H
                             + (wm*64 + mi*16 + (lane & 15)) * LDSH
                             + ks*16 + (lane >> 4) * 8);
                uint32_t ad = sbase + off * 2;
                LDM_X4(ah[mi], ad);
                LDM_X4(al[mi], ad + STG_H*2);
            }
            uint32_t bh[2][4], bl[2][4];
            #pragma unroll
            for (int np = 0; np < 2; np++) {
                uint32_t off = (uint32_t)(s * STAGE_H + 2*STG_H
                             + (wn*32 + np*16 + (lane & 7) + ((lane >> 3) & 1) * 8) * LDSH
                             + ks*16 + (lane >> 4) * 8);
                uint32_t bd = sbase + off * 2;
                LDM_X4(bh[np], bd);
                LDM_X4(bl[np], bd + STG_H*2);
            }
            #pragma unroll
            for (int mi = 0; mi < 4; mi++)
                #pragma unroll
                for (int np = 0; np < 2; np++)
                    #pragma unroll
                    for (int sub = 0; sub < 2; sub++) {
                        int nj = np * 2 + sub;
                        MMA16816(acc[mi][nj], ah[mi], bh[np][sub], bh[np][sub + 2]);
                        MMA16816(acc[mi][nj], ah[mi], bl[np][sub], bl[np][sub + 2]);
                        MMA16816(acc[mi][nj], al[mi], bh[np][sub], bh[np][sub + 2]);
                    }
        }
        __syncthreads();
    }

    #pragma unroll
    for (int mi = 0; mi < 4; mi++)
        #pragma unroll
        for (int nj = 0; nj < 4; nj++) {
            int r = row0 + wm*64 + mi*16 + (lane >> 2);
            int cc = col0 + wn*32 + nj*8 + (lane & 3) * 2;
            *(float2*)(C + (size_t)r * N + cc) =
                make_float2(acc[mi][nj][0], acc[mi][nj][1]);
            *(float2*)(C + (size_t)(r + 8) * N + cc) =
                make_float2(acc[mi][nj][2], acc[mi][nj][3]);
        }
}

// ---------------- fp32 -> bf16 hi/lo split ----------------
__global__ void split_kernel(const float* __restrict__ src,
                             __nv_bfloat16* __restrict__ hi,
                             __nv_bfloat16* __restrict__ lo, int n)
{
    int i = blockIdx.x * blockDim.x + threadIdx.x;
    if (i < n) {
        float v = src[i];
        __nv_bfloat16 h = __float2bfloat16(v);
        hi[i] = h;
        lo[i] = __float2bfloat16(v - __bfloat162float(h));
    }
}

// ---------------- SIMT fp32 GEMM (dt proj): softplus epilogue -------------
__global__ void __launch_bounds__(256, 2) sgemm_softplus(
    const float* __restrict__ A, const float* __restrict__ Bw,
    float* __restrict__ C, const float* __restrict__ bias,
    int M, int N, int K, int lda, int ldb, int ldc)
{
    __shared__ float As[8][128];
    __shared__ float Bs[8][128];
    int tid  = threadIdx.x;
    int row0 = blockIdx.y * 128;
    int col0 = blockIdx.x * 128;
    int tx = tid & 15, ty = tid >> 4;
    int ldRow = tid >> 1, ldCol = (tid & 1) * 4;

    float acc[8][8];
    #pragma unroll
    for (int i = 0; i < 8; i++)
        #pragma unroll
        for (int j = 0; j < 8; j++) acc[i][j] = 0.f;

    const float* Aptr = A + (size_t)(row0 + ldRow) * lda + ldCol;
    bool bValid = (col0 + ldRow) < N;
    const float* Bptr = Bw + (size_t)(col0 + ldRow) * ldb + ldCol;

    for (int k0 = 0; k0 < K; k0 += 8) {
        float4 av = *(const float4*)(Aptr + k0);
        float4 bv = bValid ? *(const float4*)(Bptr + k0) : make_float4(0.f,0.f,0.f,0.f);
        As[ldCol+0][ldRow] = av.x; As[ldCol+1][ldRow] = av.y;
        As[ldCol+2][ldRow] = av.z; As[ldCol+3][ldRow] = av.w;
        Bs[ldCol+0][ldRow] = bv.x; Bs[ldCol+1][ldRow] = bv.y;
        Bs[ldCol+2][ldRow] = bv.z; Bs[ldCol+3][ldRow] = bv.w;
        __syncthreads();
        #pragma unroll
        for (int kk = 0; kk < 8; kk++) {
            float a[8], b[8];
            *(float4*)(a)     = *(const float4*)&As[kk][ty*8];
            *(float4*)(a + 4) = *(const float4*)&As[kk][ty*8+4];
            *(float4*)(b)     = *(const float4*)&Bs[kk][tx*8];
            *(float4*)(b + 4) = *(const float4*)&Bs[kk][tx*8+4];
            #pragma unroll
            for (int i = 0; i < 8; i++)
                #pragma unroll
                for (int j = 0; j < 8; j++)
                    acc[i][j] = fmaf(a[i], b[j], acc[i][j]);
        }
        __syncthreads();
    }
    #pragma unroll
    for (int i = 0; i < 8; i++) {
        int r = row0 + ty*8 + i;
        #pragma unroll
        for (int j = 0; j < 8; j++) {
            int c = col0 + tx*8 + j;
            if (c < N) {
                float v = acc[i][j] + bias[c];
                v = (v > 20.f) ? v : log1pf(__expf(v));
                C[(size_t)r * ldc + c] = v;
            }
        }
    }
}

// ---------------- split-K SIMT GEMM for x_proj (partials, no atomics) ------
__global__ void __launch_bounds__(256, 2) sgemm_splitk(
    const float* __restrict__ A, const float* __restrict__ Bw,
    float* __restrict__ Cpart, int M, int N, int Kc, int lda, int ldb)
{
    __shared__ float As[8][128];
    __shared__ float Bs[8][128];
    int tid  = threadIdx.x;
    int row0 = blockIdx.y * 128;
    int col0 = blockIdx.x * 128;
    int z    = blockIdx.z;
    int tx = tid & 15, ty = tid >> 4;
    int ldRow = tid >> 1, ldCol = (tid & 1) * 4;

    float acc[8][8];
    #pragma unroll
    for (int i = 0; i < 8; i++)
        #pragma unroll
        for (int j = 0; j < 8; j++) acc[i][j] = 0.f;

    const float* Aptr = A + (size_t)(row0 + ldRow) * lda + z * Kc + ldCol;
    bool bValid = (col0 + ldRow) < N;
    const float* Bptr = Bw + (size_t)(col0 + ldRow) * ldb + z * Kc + ldCol;

    for (int k0 = 0; k0 < Kc; k0 += 8) {
        float4 av = *(const float4*)(Aptr + k0);
        float4 bv = bValid ? *(const float4*)(Bptr + k0) : make_float4(0.f,0.f,0.f,0.f);
        As[ldCol+0][ldRow] = av.x; As[ldCol+1][ldRow] = av.y;
        As[ldCol+2][ldRow] = av.z; As[ldCol+3][ldRow] = av.w;
        Bs[ldCol+0][ldRow] = bv.x; Bs[ldCol+1][ldRow] = bv.y;
        Bs[ldCol+2][ldRow] = bv.z; Bs[ldCol+3][ldRow] = bv.w;
        __syncthreads();
        #pragma unroll
        for (int kk = 0; kk < 8; kk++) {
            float a[8], b[8];
            *(float4*)(a)     = *(const float4*)&As[kk][ty*8];
            *(float4*)(a + 4) = *(const float4*)&As[kk][ty*8+4];
            *(float4*)(b)     = *(const float4*)&Bs[kk][tx*8];
            *(float4*)(b + 4) = *(const float4*)&Bs[kk][tx*8+4];
            #pragma unroll
            for (int i = 0; i < 8; i++)
                #pragma unroll
                for (int j = 0; j < 8; j++)
                    acc[i][j] = fmaf(a[i], b[j], acc[i][j]);
        }
        __syncthreads();
    }
    float* Cz = Cpart + (size_t)z * M * N;
    #pragma unroll
    for (int i = 0; i < 8; i++) {
        int r = row0 + ty*8 + i;
        #pragma unroll
        for (int j = 0; j < 8; j++) {
            int c = col0 + tx*8 + j;
            if (c < N) Cz[(size_t)r * N + c] = acc[i][j];
        }
    }
}

__global__ void reduce_splitk(float* __restrict__ dst, const float* __restrict__ parts, int n)
{
    int i = blockIdx.x * blockDim.x + threadIdx.x;
    if (i < n)
        dst[i] = parts[i] + parts[i + (size_t)n] + parts[i + 2*(size_t)n] + parts[i + 3*(size_t)n];
}

// ---------------- causal depthwise conv (k=4) + SiLU ----------------
__global__ void conv_silu_kernel(const float* __restrict__ conv_w,
                                 const float* __restrict__ conv_b)
{
    int idx = blockIdx.x * blockDim.x + threadIdx.x;
    int d = idx & (DINNER - 1);
    int m = idx >> 11;
    int l = m & (SEQ - 1);
    int b = m >> 11;
    float s = conv_b[d];
    #pragma unroll
    for (int j = 0; j < DCONV; j++) {
        int li = l - (DCONV - 1) + j;
        if (li >= 0)
            s = fmaf(conv_w[d * DCONV + j],
                     g_xz[(size_t)(b * SEQ + li) * (2 * DINNER) + d], s);
    }
    g_xc[idx] = s / (1.f + __expf(-s));
}

// ---------------- selective scan, unroll-8 latency-hiding version ----------
// lane layout: 16 lanes = 16 states of one channel; 2 channels per warp.
#define UNR 8
__global__ void __launch_bounds__(256) scan_kernel(const float* __restrict__ A_log,
                                                   const float* __restrict__ Dp)
{
    int tid  = threadIdx.x;
    int lane = tid & 31;
    int warp = tid >> 5;
    int ch = blockIdx.x * 16 + warp * 2 + (lane >> 4);
    int n  = lane & 15;
    int b  = ch >> 11;
    int d  = ch & (DINNER - 1);

    float Ac = -__expf(__ldg(A_log + d * DSTATE + n));
    float Dd = __ldg(Dp + d);
    float h  = 0.f;

    const float* dt_p = g_dt   + (size_t)b * SEQ * DINNER + d;
    const float* xc_p = g_xc   + (size_t)b * SEQ * DINNER + d;
    const float* z_p  = g_xz   + (size_t)b * SEQ * (2 * DINNER) + DINNER + d;
    const float* bc_p = g_xdbl + (size_t)b * SEQ * XDBL_W + DTRANK + n;
    size_t ybase = (size_t)b * SEQ * DINNER + d;

    for (int t0 = 0; t0 < SEQ; t0 += UNR) {
        float dtv[UNR], xv[UNR], Bn[UNR], Cn[UNR], zv[UNR];

        // batch all independent loads for UNR timesteps -> MLP ~32/lane
        #pragma unroll
        for (int u = 0; u < UNR; u++) {
            size_t t = (size_t)(t0 + u);
            dtv[u] = __ldg(dt_p + t * DINNER);
            xv[u]  = __ldg(xc_p + t * DINNER);
            Bn[u]  = __ldg(bc_p + t * XDBL_W);
            Cn[u]  = __ldg(bc_p + t * XDBL_W + DSTATE);
        }
        if (n == 0) {
            #pragma unroll
            for (int u = 0; u < UNR; u++)
                zv[u] = __ldg(z_p + (size_t)(t0 + u) * (2 * DINNER));
        }

        // independent per-u transcendental + products
        float dA[UNR], dBx[UNR];
        #pragma unroll
        for (int u = 0; u < UNR; u++) {
            dA[u]  = __expf(dtv[u] * Ac);
            dBx[u] = dtv[u] * Bn[u] * xv[u];
        }

        // serial recurrence (only true dependency chain: 1 fma per step)
        float p[UNR];
        #pragma unroll
        for (int u = 0; u < UNR; u++) {
            h = fmaf(dA[u], h, dBx[u]);
            p[u] = h * Cn[u];
        }

        // independent 16-lane reductions
        #pragma unroll
        for (int u = 0; u < UNR; u++) {
            p[u] += __shfl_xor_sync(0xffffffffu, p[u], 8);
            p[u] += __shfl_xor_sync(0xffffffffu, p[u], 4);
            p[u] += __shfl_xor_sync(0xffffffffu, p[u], 2);
            p[u] += __shfl_xor_sync(0xffffffffu, p[u], 1);
        }

        if (n == 0) {
            #pragma unroll
            for (int u = 0; u < UNR; u++) {
                float yv = fmaf(Dd, xv[u], p[u]);
                yv *= zv[u] / (1.f + __expf(-zv[u]));
                __nv_bfloat16 hh = __float2bfloat16(yv);
                g_yh[ybase + (size_t)(t0 + u) * DINNER] = hh;
                g_yl[ybase + (size_t)(t0 + u) * DINNER] =
                    __float2bfloat16(yv - __bfloat162float(hh));
            }
        }
    }
}

// ---------------- launch ----------------
extern "C" void kernel_launch(void* const* d_in, const int* in_sizes, int n_in,
                              void* d_out, int out_size)
{
    const float* x          = (const float*)d_in[0];
    const float* in_proj_w  = (const float*)d_in[1];
    const float* conv_w     = (const float*)d_in[2];
    const float* conv_b     = (const float*)d_in[3];
    const float* A_log      = (const float*)d_in[4];
    const float* Dp         = (const float*)d_in[5];
    const float* x_proj_w   = (const float*)d_in[6];
    const float* dt_proj_w  = (const float*)d_in[7];
    const float* dt_proj_b  = (const float*)d_in[8];
    const float* out_proj_w = (const float*)d_in[9];
    float*       out        = (float*)d_out;

    float *xz, *xc, *xdbl, *xdblp, *dt;
    __nv_bfloat16 *xh, *xl, *wih, *wil, *yh, *yl, *woh, *wol;
    cudaGetSymbolAddress((void**)&xz,    g_xz);
    cudaGetSymbolAddress((void**)&xc,    g_xc);
    cudaGetSymbolAddress((void**)&xdbl,  g_xdbl);
    cudaGetSymbolAddress((void**)&xdblp, g_xdblp);
    cudaGetSymbolAddress((void**)&dt,    g_dt);
    cudaGetSymbolAddress((void**)&xh,  g_xh);
    cudaGetSymbolAddress((void**)&xl,  g_xl);
    cudaGetSymbolAddress((void**)&wih, g_wih);
    cudaGetSymbolAddress((void**)&wil, g_wil);
    cudaGetSymbolAddress((void**)&yh,  g_yh);
    cudaGetSymbolAddress((void**)&yl,  g_yl);
    cudaGetSymbolAddress((void**)&woh, g_woh);
    cudaGetSymbolAddress((void**)&wol, g_wol);

    cudaFuncSetAttribute(hmma_gemm, cudaFuncAttributeMaxDynamicSharedMemorySize,
                         HMMA_SMEM);

    // 0) bf16 hi/lo splits
    split_kernel<<<(MROWS*DMODEL + 255)/256, 256>>>(x, xh, xl, MROWS*DMODEL);
    split_kernel<<<(2*DINNER*DMODEL + 255)/256, 256>>>(in_proj_w, wih, wil, 2*DINNER*DMODEL);
    split_kernel<<<(DMODEL*DINNER + 255)/256, 256>>>(out_proj_w, woh, wol, DMODEL*DINNER);

    // 1) xz = x @ in_proj_w^T  [4096, 4096], K=1024 — HMMA split-bf16
    hmma_gemm<<<dim3(32, 32), 256, HMMA_SMEM>>>(xh, xl, wih, wil, xz, DMODEL, 2*DINNER);

    // 2) causal depthwise conv + silu  -> g_xc
    conv_silu_kernel<<<(MROWS * DINNER) / 256, 256>>>(conv_w, conv_b);

    // 3) x_dbl = xc @ x_proj_w^T  [4096, 96], K=2048 — split-K x4 + reduce
    sgemm_splitk<<<dim3(1, 32, KSPLIT), 256>>>(xc, x_proj_w, xdblp,
                                               MROWS, XDBL_W, DINNER/KSPLIT,
                                               DINNER, DINNER);
    reduce_splitk<<<(MROWS*XDBL_W + 255)/256, 256>>>(xdbl, xdblp, MROWS*XDBL_W);

    // 4) dt = softplus(x_dbl[:, :64] @ dt_proj_w^T + b)   [4096, 2048], K=64
    sgemm_softplus<<<dim3(16, 32), 256>>>(xdbl, dt_proj_w, dt, dt_proj_b,
                                          MROWS, DINNER, DTRANK,
                                          XDBL_W, DTRANK, DINNER);

    // 5) selective scan + D*x + silu(z) gate  -> g_yh/g_yl
    scan_kernel<<<256, 256>>>(A_log, Dp);

    // 6) out = y @ out_proj_w^T  [4096, 1024], K=2048 — HMMA split-bf16
    hmma_gemm<<<dim3(8, 32), 256, HMMA_SMEM>>>(yh, yl, woh, wol, out, DINNER, DMODEL);
}

// round 5
// speedup vs baseline: 3.0335x; 1.0591x over previous
#include <cuda_runtime.h>
#include <cuda_bf16.h>
#include <math.h>
#include <stdint.h>

#define B_SZ   2
#define SEQ    2048
#define DMODEL 1024
#define DINNER 2048
#define DSTATE 16
#define DTRANK 64
#define DCONV  4
#define MROWS  (B_SZ*SEQ)   // 4096
#define XDBL_W 96
#define KSPLIT 4

// ---------------- scratch ----------------
__device__ float g_xz   [(size_t)MROWS * 2 * DINNER];
__device__ float g_xc   [(size_t)MROWS * DINNER];
__device__ float g_xdbl [(size_t)MROWS * XDBL_W];
__device__ float g_xdblp[(size_t)KSPLIT * MROWS * XDBL_W];
__device__ float g_dt   [(size_t)MROWS * DINNER];

// channel-major transposed arrays for the scan
__device__ float g_dtT  [(size_t)MROWS * DINNER];
__device__ float g_xcT  [(size_t)MROWS * DINNER];
__device__ float g_zsT  [(size_t)MROWS * DINNER];
__device__ float g_BT   [(size_t)B_SZ * DSTATE * SEQ];
__device__ float g_CT   [(size_t)B_SZ * DSTATE * SEQ];

// bf16 hi/lo splits
__device__ __nv_bfloat16 g_xh [(size_t)MROWS * DMODEL];
__device__ __nv_bfloat16 g_xl [(size_t)MROWS * DMODEL];
__device__ __nv_bfloat16 g_wih[(size_t)(2*DINNER) * DMODEL];
__device__ __nv_bfloat16 g_wil[(size_t)(2*DINNER) * DMODEL];
__device__ __nv_bfloat16 g_yh [(size_t)MROWS * DINNER];
__device__ __nv_bfloat16 g_yl [(size_t)MROWS * DINNER];
__device__ __nv_bfloat16 g_woh[(size_t)DMODEL * DINNER];
__device__ __nv_bfloat16 g_wol[(size_t)DMODEL * DINNER];

// ======================= helpers =======================
__device__ __forceinline__ uint32_t smem_to_u32(const void* p) {
    uint32_t a;
    asm("{ .reg .u64 t; cvta.to.shared.u64 t, %1; cvt.u32.u64 %0, t; }"
        : "=r"(a) : "l"(p));
    return a;
}

#define LDM_X4(r, addr) \
    asm volatile("ldmatrix.sync.aligned.m8n8.x4.shared.b16 {%0,%1,%2,%3}, [%4];" \
        : "=r"((r)[0]), "=r"((r)[1]), "=r"((r)[2]), "=r"((r)[3]) : "r"(addr))

#define MMA16816(c, a, b0, b1) \
    asm volatile("mma.sync.aligned.m16n8k16.row.col.f32.bf16.bf16.f32 " \
        "{%0,%1,%2,%3}, {%4,%5,%6,%7}, {%8,%9}, {%0,%1,%2,%3};" \
        : "+f"((c)[0]), "+f"((c)[1]), "+f"((c)[2]), "+f"((c)[3]) \
        : "r"((a)[0]), "r"((a)[1]), "r"((a)[2]), "r"((a)[3]), "r"(b0), "r"(b1))

#define CP_ASYNC16(saddr, gptr) \
    asm volatile("cp.async.cg.shared.global [%0], [%1], 16;" \
        :: "r"(saddr), "l"(gptr) : "memory")
#define CP_COMMIT() asm volatile("cp.async.commit_group;" ::: "memory")
#define CP_WAIT(n)  asm volatile("cp.async.wait_group %0;" :: "n"(n) : "memory")

// ================= split-bf16 HMMA GEMM, 3-stage pipeline =================
#define LDSH   40
#define STG_H  (128*LDSH)
#define STAGE_H (4*STG_H)
#define NSTAGE 3
#define HMMA_SMEM (NSTAGE*STAGE_H*2)   // 122880 bytes

__global__ void __launch_bounds__(256, 1)
hmma_gemm(const __nv_bfloat16* __restrict__ Ah, const __nv_bfloat16* __restrict__ Al,
          const __nv_bfloat16* __restrict__ Bh, const __nv_bfloat16* __restrict__ Bl,
          float* __restrict__ C, int K, int N)
{
    extern __shared__ __nv_bfloat16 sm[];
    const int tid  = threadIdx.x;
    const int lane = tid & 31;
    const int w    = tid >> 5;
    const int wm   = w >> 2;
    const int wn   = w & 3;
    const int row0 = blockIdx.y * 128;
    const int col0 = blockIdx.x * 128;
    const uint32_t sbase = smem_to_u32(sm);

    const int nc = K >> 5;

    auto load_stage = [&](int c, int s) {
        #pragma unroll
        for (int j = 0; j < 2; j++) {
            int i = tid + j * 256;
            int r = i >> 2, q = i & 3;
            size_t gA = (size_t)(row0 + r) * K + c * 32 + q * 8;
            size_t gB = (size_t)(col0 + r) * K + c * 32 + q * 8;
            uint32_t so = (uint32_t)(s * STAGE_H + r * LDSH + q * 8);
            uint32_t sa = sbase + so * 2;
            CP_ASYNC16(sa,                (const void*)(Ah + gA));
            CP_ASYNC16(sa + STG_H*2,      (const void*)(Al + gA));
            CP_ASYNC16(sa + 2*STG_H*2,    (const void*)(Bh + gB));
            CP_ASYNC16(sa + 3*STG_H*2,    (const void*)(Bl + gB));
        }
    };

    float acc[4][4][4];
    #pragma unroll
    for (int mi = 0; mi < 4; mi++)
        #pragma unroll
        for (int nj = 0; nj < 4; nj++)
            #pragma unroll
            for (int q = 0; q < 4; q++) acc[mi][nj][q] = 0.f;

    load_stage(0, 0); CP_COMMIT();
    load_stage(1, 1); CP_COMMIT();

    for (int c = 0; c < nc; c++) {
        int s = c % NSTAGE;
        if (c + 2 < nc) load_stage(c + 2, (c + 2) % NSTAGE);
        CP_COMMIT();
        CP_WAIT(2);
        __syncthreads();

        #pragma unroll
        for (int ks = 0; ks < 2; ks++) {
            uint32_t ah[4][4], al[4][4];
            #pragma unroll
            for (int mi = 0; mi < 4; mi++) {
                uint32_t off = (uint32_t)(s * STAGE_H
                             + (wm*64 + mi*16 + (lane & 15)) * LDSH
                             + ks*16 + (lane >> 4) * 8);
                uint32_t ad = sbase + off * 2;
                LDM_X4(ah[mi], ad);
                LDM_X4(al[mi], ad + STG_H*2);
            }
            uint32_t bh[2][4], bl[2][4];
            #pragma unroll
            for (int np = 0; np < 2; np++) {
                uint32_t off = (uint32_t)(s * STAGE_H + 2*STG_H
                             + (wn*32 + np*16 + (lane & 7) + ((lane >> 3) & 1) * 8) * LDSH
                             + ks*16 + (lane >> 4) * 8);
                uint32_t bd = sbase + off * 2;
                LDM_X4(bh[np], bd);
                LDM_X4(bl[np], bd + STG_H*2);
            }
            #pragma unroll
            for (int mi = 0; mi < 4; mi++)
                #pragma unroll
                for (int np = 0; np < 2; np++)
                    #pragma unroll
                    for (int sub = 0; sub < 2; sub++) {
                        int nj = np * 2 + sub;
                        MMA16816(acc[mi][nj], ah[mi], bh[np][sub], bh[np][sub + 2]);
                        MMA16816(acc[mi][nj], ah[mi], bl[np][sub], bl[np][sub + 2]);
                        MMA16816(acc[mi][nj], al[mi], bh[np][sub], bh[np][sub + 2]);
                    }
        }
        __syncthreads();
    }

    #pragma unroll
    for (int mi = 0; mi < 4; mi++)
        #pragma unroll
        for (int nj = 0; nj < 4; nj++) {
            int r = row0 + wm*64 + mi*16 + (lane >> 2);
            int cc = col0 + wn*32 + nj*8 + (lane & 3) * 2;
            *(float2*)(C + (size_t)r * N + cc) =
                make_float2(acc[mi][nj][0], acc[mi][nj][1]);
            *(float2*)(C + (size_t)(r + 8) * N + cc) =
                make_float2(acc[mi][nj][2], acc[mi][nj][3]);
        }
}

// ---------------- fp32 -> bf16 hi/lo split ----------------
__global__ void split_kernel(const float* __restrict__ src,
                             __nv_bfloat16* __restrict__ hi,
                             __nv_bfloat16* __restrict__ lo, int n)
{
    int i = blockIdx.x * blockDim.x + threadIdx.x;
    if (i < n) {
        float v = src[i];
        __nv_bfloat16 h = __float2bfloat16(v);
        hi[i] = h;
        lo[i] = __float2bfloat16(v - __bfloat162float(h));
    }
}

// ---------------- SIMT fp32 GEMM (dt proj): softplus epilogue -------------
__global__ void __launch_bounds__(256, 2) sgemm_softplus(
    const float* __restrict__ A, const float* __restrict__ Bw,
    float* __restrict__ C, const float* __restrict__ bias,
    int M, int N, int K, int lda, int ldb, int ldc)
{
    __shared__ float As[8][128];
    __shared__ float Bs[8][128];
    int tid  = threadIdx.x;
    int row0 = blockIdx.y * 128;
    int col0 = blockIdx.x * 128;
    int tx = tid & 15, ty = tid >> 4;
    int ldRow = tid >> 1, ldCol = (tid & 1) * 4;

    float acc[8][8];
    #pragma unroll
    for (int i = 0; i < 8; i++)
        #pragma unroll
        for (int j = 0; j < 8; j++) acc[i][j] = 0.f;

    const float* Aptr = A + (size_t)(row0 + ldRow) * lda + ldCol;
    bool bValid = (col0 + ldRow) < N;
    const float* Bptr = Bw + (size_t)(col0 + ldRow) * ldb + ldCol;

    for (int k0 = 0; k0 < K; k0 += 8) {
        float4 av = *(const float4*)(Aptr + k0);
        float4 bv = bValid ? *(const float4*)(Bptr + k0) : make_float4(0.f,0.f,0.f,0.f);
        As[ldCol+0][ldRow] = av.x; As[ldCol+1][ldRow] = av.y;
        As[ldCol+2][ldRow] = av.z; As[ldCol+3][ldRow] = av.w;
        Bs[ldCol+0][ldRow] = bv.x; Bs[ldCol+1][ldRow] = bv.y;
        Bs[ldCol+2][ldRow] = bv.z; Bs[ldCol+3][ldRow] = bv.w;
        __syncthreads();
        #pragma unroll
        for (int kk = 0; kk < 8; kk++) {
            float a[8], b[8];
            *(float4*)(a)     = *(const float4*)&As[kk][ty*8];
            *(float4*)(a + 4) = *(const float4*)&As[kk][ty*8+4];
            *(float4*)(b)     = *(const float4*)&Bs[kk][tx*8];
            *(float4*)(b + 4) = *(const float4*)&Bs[kk][tx*8+4];
            #pragma unroll
            for (int i = 0; i < 8; i++)
                #pragma unroll
                for (int j = 0; j < 8; j++)
                    acc[i][j] = fmaf(a[i], b[j], acc[i][j]);
        }
        __syncthreads();
    }
    #pragma unroll
    for (int i = 0; i < 8; i++) {
        int r = row0 + ty*8 + i;
        #pragma unroll
        for (int j = 0; j < 8; j++) {
            int c = col0 + tx*8 + j;
            if (c < N) {
                float v = acc[i][j] + bias[c];
                v = (v > 20.f) ? v : log1pf(__expf(v));
                C[(size_t)r * ldc + c] = v;
            }
        }
    }
}

// ---------------- split-K SIMT GEMM for x_proj ------
__global__ void __launch_bounds__(256, 2) sgemm_splitk(
    const float* __restrict__ A, const float* __restrict__ Bw,
    float* __restrict__ Cpart, int M, int N, int Kc, int lda, int ldb)
{
    __shared__ float As[8][128];
    __shared__ float Bs[8][128];
    int tid  = threadIdx.x;
    int row0 = blockIdx.y * 128;
    int col0 = blockIdx.x * 128;
    int z    = blockIdx.z;
    int tx = tid & 15, ty = tid >> 4;
    int ldRow = tid >> 1, ldCol = (tid & 1) * 4;

    float acc[8][8];
    #pragma unroll
    for (int i = 0; i < 8; i++)
        #pragma unroll
        for (int j = 0; j < 8; j++) acc[i][j] = 0.f;

    const float* Aptr = A + (size_t)(row0 + ldRow) * lda + z * Kc + ldCol;
    bool bValid = (col0 + ldRow) < N;
    const float* Bptr = Bw + (size_t)(col0 + ldRow) * ldb + z * Kc + ldCol;

    for (int k0 = 0; k0 < Kc; k0 += 8) {
        float4 av = *(const float4*)(Aptr + k0);
        float4 bv = bValid ? *(const float4*)(Bptr + k0) : make_float4(0.f,0.f,0.f,0.f);
        As[ldCol+0][ldRow] = av.x; As[ldCol+1][ldRow] = av.y;
        As[ldCol+2][ldRow] = av.z; As[ldCol+3][ldRow] = av.w;
        Bs[ldCol+0][ldRow] = bv.x; Bs[ldCol+1][ldRow] = bv.y;
        Bs[ldCol+2][ldRow] = bv.z; Bs[ldCol+3][ldRow] = bv.w;
        __syncthreads();
        #pragma unroll
        for (int kk = 0; kk < 8; kk++) {
            float a[8], b[8];
            *(float4*)(a)     = *(const float4*)&As[kk][ty*8];
            *(float4*)(a + 4) = *(const float4*)&As[kk][ty*8+4];
            *(float4*)(b)     = *(const float4*)&Bs[kk][tx*8];
            *(float4*)(b + 4) = *(const float4*)&Bs[kk][tx*8+4];
            #pragma unroll
            for (int i = 0; i < 8; i++)
                #pragma unroll
                for (int j = 0; j < 8; j++)
                    acc[i][j] = fmaf(a[i], b[j], acc[i][j]);
        }
        __syncthreads();
    }
    float* Cz = Cpart + (size_t)z * M * N;
    #pragma unroll
    for (int i = 0; i < 8; i++) {
        int r = row0 + ty*8 + i;
        #pragma unroll
        for (int j = 0; j < 8; j++) {
            int c = col0 + tx*8 + j;
            if (c < N) Cz[(size_t)r * N + c] = acc[i][j];
        }
    }
}

// reduce split-K partials; route dt cols to xdbl, B/C cols to transposed arrays
__global__ void reduce_splitk_T(const float* __restrict__ parts)
{
    const int total = MROWS * XDBL_W;
    int i = blockIdx.x * blockDim.x + threadIdx.x;
    if (i >= total) return;
    float v = parts[i] + parts[i + (size_t)total] +
              parts[i + 2*(size_t)total] + parts[i + 3*(size_t)total];
    int m = i / XDBL_W;
    int c = i - m * XDBL_W;
    if (c < DTRANK) {
        g_xdbl[i] = v;
    } else {
        int b = m >> 11, t = m & (SEQ - 1);
        int cc = c - DTRANK;          // 0..31
        if (cc < DSTATE) g_BT[(size_t)(b*DSTATE + cc) * SEQ + t] = v;
        else             g_CT[(size_t)(b*DSTATE + cc - DSTATE) * SEQ + t] = v;
    }
}

// ---------------- causal depthwise conv (k=4) + SiLU ----------------
__global__ void conv_silu_kernel(const float* __restrict__ conv_w,
                                 const float* __restrict__ conv_b)
{
    int idx = blockIdx.x * blockDim.x + threadIdx.x;
    int d = idx & (DINNER - 1);
    int m = idx >> 11;
    int l = m & (SEQ - 1);
    int b = m >> 11;
    float s = conv_b[d];
    #pragma unroll
    for (int j = 0; j < DCONV; j++) {
        int li = l - (DCONV - 1) + j;
        if (li >= 0)
            s = fmaf(conv_w[d * DCONV + j],
                     g_xz[(size_t)(b * SEQ + li) * (2 * DINNER) + d], s);
    }
    g_xc[idx] = s / (1.f + __expf(-s));
}

// ---------------- batched tiled transpose: dt->dtT, xc->xcT, silu(z)->zsT ----
__global__ void __launch_bounds__(256) transpose3_kernel()
{
    __shared__ float tile[32][33];
    int zsel = blockIdx.z;
    int b  = blockIdx.y >> 6;
    int t0 = (blockIdx.y & 63) << 5;
    int d0 = blockIdx.x << 5;
    int tx = threadIdx.x & 31, ty = threadIdx.x >> 5;   // 32 x 8

    const float* src; int stride;
    if (zsel == 0)      { src = g_dt;          stride = DINNER;   }
    else if (zsel == 1) { src = g_xc;          stride = DINNER;   }
    else                { src = g_xz + DINNER; stride = 2*DINNER; }

    #pragma unroll
    for (int k = 0; k < 32; k += 8) {
        float v = src[(size_t)(b*SEQ + t0 + ty + k) * stride + d0 + tx];
        if (zsel == 2) v = v / (1.f + __expf(-v));
        tile[ty + k][tx] = v;
    }
    __syncthreads();
    float* dst = (zsel == 0) ? g_dtT : (zsel == 1) ? g_xcT : g_zsT;
    #pragma unroll
    for (int k = 0; k < 32; k += 8)
        dst[(size_t)(b*DINNER + d0 + ty + k) * SEQ + t0 + tx] = tile[tx][ty + k];
}

// ---------------- selective scan v3: channel-major, UNR=16 ----------------
#define UNR2 16
__global__ void __launch_bounds__(256) scan_kernel(const float* __restrict__ A_log,
                                                   const float* __restrict__ Dp)
{
    int tid  = threadIdx.x;
    int lane = tid & 31;
    int warp = tid >> 5;
    int c2 = lane >> 4;
    int n  = lane & 15;
    int ch = blockIdx.x * 16 + warp * 2 + c2;
    int b  = ch >> 11;
    int d  = ch & (DINNER - 1);

    float Ac = -__expf(__ldg(A_log + d * DSTATE + n));
    float Dd = __ldg(Dp + d);
    float h  = 0.f;

    const float* dtT = g_dtT + (size_t)ch * SEQ;
    const float* xT  = g_xcT + (size_t)ch * SEQ;
    const float* zT  = g_zsT + (size_t)ch * SEQ;
    const float* BT  = g_BT  + (size_t)(b * DSTATE + n) * SEQ;
    const float* CT  = g_CT  + (size_t)(b * DSTATE + n) * SEQ;
    int srcbase = c2 << 4;

    for (int t0 = 0; t0 < SEQ; t0 += UNR2) {
        float dt_l = __ldg(dtT + t0 + n);
        float x_l  = __ldg(xT  + t0 + n);
        float z_l  = __ldg(zT  + t0 + n);

        float Bn[UNR2], Cn[UNR2];
        #pragma unroll
        for (int q = 0; q < UNR2; q += 4) {
            float4 bq = *(const float4*)(BT + t0 + q);
            float4 cq = *(const float4*)(CT + t0 + q);
            Bn[q] = bq.x; Bn[q+1] = bq.y; Bn[q+2] = bq.z; Bn[q+3] = bq.w;
            Cn[q] = cq.x; Cn[q+1] = cq.y; Cn[q+2] = cq.z; Cn[q+3] = cq.w;
        }

        float dtv[UNR2], xv[UNR2];
        #pragma unroll
        for (int u = 0; u < UNR2; u++) {
            dtv[u] = __shfl_sync(0xffffffffu, dt_l, srcbase + u);
            xv[u]  = __shfl_sync(0xffffffffu, x_l,  srcbase + u);
        }

        // dBx into Bn, dA into dtv (independent per u)
        #pragma unroll
        for (int u = 0; u < UNR2; u++) {
            Bn[u]  = dtv[u] * Bn[u] * xv[u];
            dtv[u] = __expf(dtv[u] * Ac);
        }

        // serial recurrence + C projection
        float p[UNR2];
        #pragma unroll
        for (int u = 0; u < UNR2; u++) {
            h = fmaf(dtv[u], h, Bn[u]);
            p[u] = h * Cn[u];
        }

        // 16-lane reductions (stay within each half-warp)
        #pragma unroll
        for (int u = 0; u < UNR2; u++) {
            p[u] += __shfl_xor_sync(0xffffffffu, p[u], 8);
            p[u] += __shfl_xor_sync(0xffffffffu, p[u], 4);
            p[u] += __shfl_xor_sync(0xffffffffu, p[u], 2);
            p[u] += __shfl_xor_sync(0xffffffffu, p[u], 1);
        }

        // lane n keeps p[n] (compile-time select chain, no dynamic indexing)
        float ps = p[0];
        #pragma unroll
        for (int u = 1; u < UNR2; u++) ps = (n == u) ? p[u] : ps;

        float yv = fmaf(Dd, x_l, ps) * z_l;    // x_l = x[t0+n], z_l = silu(z)[t0+n]
        __nv_bfloat16 hh = __float2bfloat16(yv);
        size_t oy = (size_t)(b * SEQ + t0 + n) * DINNER + d;
        g_yh[oy] = hh;
        g_yl[oy] = __float2bfloat16(yv - __bfloat162float(hh));
    }
}

// ---------------- launch ----------------
extern "C" void kernel_launch(void* const* d_in, const int* in_sizes, int n_in,
                              void* d_out, int out_size)
{
    const float* x          = (const float*)d_in[0];
    const float* in_proj_w  = (const float*)d_in[1];
    const float* conv_w     = (const float*)d_in[2];
    const float* conv_b     = (const float*)d_in[3];
    const float* A_log      = (const float*)d_in[4];
    const float* Dp         = (const float*)d_in[5];
    const float* x_proj_w   = (const float*)d_in[6];
    const float* dt_proj_w  = (const float*)d_in[7];
    const float* dt_proj_b  = (const float*)d_in[8];
    const float* out_proj_w = (const float*)d_in[9];
    float*       out        = (float*)d_out;

    float *xz, *xc, *xdbl, *xdblp, *dt;
    __nv_bfloat16 *xh, *xl, *wih, *wil, *yh, *yl, *woh, *wol;
    cudaGetSymbolAddress((void**)&xz,    g_xz);
    cudaGetSymbolAddress((void**)&xc,    g_xc);
    cudaGetSymbolAddress((void**)&xdbl,  g_xdbl);
    cudaGetSymbolAddress((void**)&xdblp, g_xdblp);
    cudaGetSymbolAddress((void**)&dt,    g_dt);
    cudaGetSymbolAddress((void**)&xh,  g_xh);
    cudaGetSymbolAddress((void**)&xl,  g_xl);
    cudaGetSymbolAddress((void**)&wih, g_wih);
    cudaGetSymbolAddress((void**)&wil, g_wil);
    cudaGetSymbolAddress((void**)&yh,  g_yh);
    cudaGetSymbolAddress((void**)&yl,  g_yl);
    cudaGetSymbolAddress((void**)&woh, g_woh);
    cudaGetSymbolAddress((void**)&wol, g_wol);

    cudaFuncSetAttribute(hmma_gemm, cudaFuncAttributeMaxDynamicSharedMemorySize,
                         HMMA_SMEM);

    // 0) bf16 hi/lo splits
    split_kernel<<<(MROWS*DMODEL + 255)/256, 256>>>(x, xh, xl, MROWS*DMODEL);
    split_kernel<<<(2*DINNER*DMODEL + 255)/256, 256>>>(in_proj_w, wih, wil, 2*DINNER*DMODEL);
    split_kernel<<<(DMODEL*DINNER + 255)/256, 256>>>(out_proj_w, woh, wol, DMODEL*DINNER);

    // 1) xz = x @ in_proj_w^T
    hmma_gemm<<<dim3(32, 32), 256, HMMA_SMEM>>>(xh, xl, wih, wil, xz, DMODEL, 2*DINNER);

    // 2) causal depthwise conv + silu
    conv_silu_kernel<<<(MROWS * DINNER) / 256, 256>>>(conv_w, conv_b);

    // 3) x_dbl = xc @ x_proj_w^T  — split-K x4 + routed reduce (B,C transposed)
    sgemm_splitk<<<dim3(1, 32, KSPLIT), 256>>>(xc, x_proj_w, xdblp,
                                               MROWS, XDBL_W, DINNER/KSPLIT,
                                               DINNER, DINNER);
    reduce_splitk_T<<<(MROWS*XDBL_W + 255)/256, 256>>>(xdblp);

    // 4) dt = softplus(x_dbl[:, :64] @ dt_proj_w^T + b)
    sgemm_softplus<<<dim3(16, 32), 256>>>(xdbl, dt_proj_w, dt, dt_proj_b,
                                          MROWS, DINNER, DTRANK,
                                          XDBL_W, DTRANK, DINNER);

    // 4b) transposes: dt->dtT, xc->xcT, silu(z)->zsT
    transpose3_kernel<<<dim3(64, 128, 3), 256>>>();

    // 5) selective scan v3 (channel-major)
    scan_kernel<<<256, 256>>>(A_log, Dp);

    // 6) out = y @ out_proj_w^T
    hmma_gemm<<<dim3(8, 32), 256, HMMA_SMEM>>>(yh, yl, woh, wol, out, DINNER, DMODEL);
}

// round 6
// speedup vs baseline: 3.3236x; 1.0956x over previous
#include <cuda_runtime.h>
#include <cuda_bf16.h>
#include <math.h>
#include <stdint.h>

#define B_SZ   2
#define SEQ    2048
#define DMODEL 1024
#define DINNER 2048
#define DSTATE 16
#define DTRANK 64
#define DCONV  4
#define MROWS  (B_SZ*SEQ)   // 4096
#define XDBL_W 96
#define KSPLIT 4

// ---------------- scratch ----------------
__device__ float g_xz   [(size_t)MROWS * 2 * DINNER];
__device__ float g_xc   [(size_t)MROWS * DINNER];
__device__ float g_xdbl [(size_t)MROWS * XDBL_W];
__device__ float g_xdblp[(size_t)KSPLIT * MROWS * XDBL_W];
__device__ float g_dt   [(size_t)MROWS * DINNER];

// channel-major transposed arrays for the scan
__device__ float g_dtT  [(size_t)MROWS * DINNER];
__device__ float g_xcT  [(size_t)MROWS * DINNER];
__device__ float g_zsT  [(size_t)MROWS * DINNER];
__device__ float g_BT   [(size_t)B_SZ * DSTATE * SEQ];
__device__ float g_CT   [(size_t)B_SZ * DSTATE * SEQ];

// bf16 hi/lo splits
__device__ __nv_bfloat16 g_xh [(size_t)MROWS * DMODEL];
__device__ __nv_bfloat16 g_xl [(size_t)MROWS * DMODEL];
__device__ __nv_bfloat16 g_wih[(size_t)(2*DINNER) * DMODEL];
__device__ __nv_bfloat16 g_wil[(size_t)(2*DINNER) * DMODEL];
__device__ __nv_bfloat16 g_yh [(size_t)MROWS * DINNER];
__device__ __nv_bfloat16 g_yl [(size_t)MROWS * DINNER];
__device__ __nv_bfloat16 g_woh[(size_t)DMODEL * DINNER];
__device__ __nv_bfloat16 g_wol[(size_t)DMODEL * DINNER];

// ======================= helpers =======================
__device__ __forceinline__ uint32_t smem_to_u32(const void* p) {
    uint32_t a;
    asm("{ .reg .u64 t; cvta.to.shared.u64 t, %1; cvt.u32.u64 %0, t; }"
        : "=r"(a) : "l"(p));
    return a;
}

#define LDM_X4(r, addr) \
    asm volatile("ldmatrix.sync.aligned.m8n8.x4.shared.b16 {%0,%1,%2,%3}, [%4];" \
        : "=r"((r)[0]), "=r"((r)[1]), "=r"((r)[2]), "=r"((r)[3]) : "r"(addr))

#define MMA16816(c, a, b0, b1) \
    asm volatile("mma.sync.aligned.m16n8k16.row.col.f32.bf16.bf16.f32 " \
        "{%0,%1,%2,%3}, {%4,%5,%6,%7}, {%8,%9}, {%0,%1,%2,%3};" \
        : "+f"((c)[0]), "+f"((c)[1]), "+f"((c)[2]), "+f"((c)[3]) \
        : "r"((a)[0]), "r"((a)[1]), "r"((a)[2]), "r"((a)[3]), "r"(b0), "r"(b1))

#define CP_ASYNC16(saddr, gptr) \
    asm volatile("cp.async.cg.shared.global [%0], [%1], 16;" \
        :: "r"(saddr), "l"(gptr) : "memory")
#define CP_COMMIT() asm volatile("cp.async.commit_group;" ::: "memory")
#define CP_WAIT(n)  asm volatile("cp.async.wait_group %0;" :: "n"(n) : "memory")

// ================= split-bf16 HMMA GEMM, 2-stage (R4 config) =================
#define LDSH   40
#define STG_H  (128*LDSH)
#define STAGE_H (4*STG_H)
#define HMMA_SMEM (2*STAGE_H*2)      // 81920 bytes -> 2 CTAs/SM

__global__ void __launch_bounds__(256, 1)
hmma_gemm(const __nv_bfloat16* __restrict__ Ah, const __nv_bfloat16* __restrict__ Al,
          const __nv_bfloat16* __restrict__ Bh, const __nv_bfloat16* __restrict__ Bl,
          float* __restrict__ C, int K, int N)
{
    extern __shared__ __nv_bfloat16 sm[];
    const int tid  = threadIdx.x;
    const int lane = tid & 31;
    const int w    = tid >> 5;
    const int wm   = w >> 2;
    const int wn   = w & 3;
    const int row0 = blockIdx.y * 128;
    const int col0 = blockIdx.x * 128;
    const uint32_t sbase = smem_to_u32(sm);

    const int nc = K >> 5;

    auto load_stage = [&](int c, int s) {
        #pragma unroll
        for (int j = 0; j < 2; j++) {
            int i = tid + j * 256;
            int r = i >> 2, q = i & 3;
            size_t gA = (size_t)(row0 + r) * K + c * 32 + q * 8;
            size_t gB = (size_t)(col0 + r) * K + c * 32 + q * 8;
            uint32_t so = (uint32_t)(s * STAGE_H + r * LDSH + q * 8);
            uint32_t sa = sbase + so * 2;
            CP_ASYNC16(sa,                (const void*)(Ah + gA));
            CP_ASYNC16(sa + STG_H*2,      (const void*)(Al + gA));
            CP_ASYNC16(sa + 2*STG_H*2,    (const void*)(Bh + gB));
            CP_ASYNC16(sa + 3*STG_H*2,    (const void*)(Bl + gB));
        }
    };

    float acc[4][4][4];
    #pragma unroll
    for (int mi = 0; mi < 4; mi++)
        #pragma unroll
        for (int nj = 0; nj < 4; nj++)
            #pragma unroll
            for (int q = 0; q < 4; q++) acc[mi][nj][q] = 0.f;

    load_stage(0, 0);
    CP_COMMIT();

    for (int c = 0; c < nc; c++) {
        int s = c & 1;
        if (c + 1 < nc) {
            load_stage(c + 1, (c + 1) & 1);
            CP_COMMIT();
            CP_WAIT(1);
        } else {
            CP_WAIT(0);
        }
        __syncthreads();

        #pragma unroll
        for (int ks = 0; ks < 2; ks++) {
            uint32_t ah[4][4], al[4][4];
            #pragma unroll
            for (int mi = 0; mi < 4; mi++) {
                uint32_t off = (uint32_t)(s * STAGE_H
                             + (wm*64 + mi*16 + (lane & 15)) * LDSH
                             + ks*16 + (lane >> 4) * 8);
                uint32_t ad = sbase + off * 2;
                LDM_X4(ah[mi], ad);
                LDM_X4(al[mi], ad + STG_H*2);
            }
            uint32_t bh[2][4], bl[2][4];
            #pragma unroll
            for (int np = 0; np < 2; np++) {
                uint32_t off = (uint32_t)(s * STAGE_H + 2*STG_H
                             + (wn*32 + np*16 + (lane & 7) + ((lane >> 3) & 1) * 8) * LDSH
                             + ks*16 + (lane >> 4) * 8);
                uint32_t bd = sbase + off * 2;
                LDM_X4(bh[np], bd);
                LDM_X4(bl[np], bd + STG_H*2);
            }
            #pragma unroll
            for (int mi = 0; mi < 4; mi++)
                #pragma unroll
                for (int np = 0; np < 2; np++)
                    #pragma unroll
                    for (int sub = 0; sub < 2; sub++) {
                        int nj = np * 2 + sub;
                        MMA16816(acc[mi][nj], ah[mi], bh[np][sub], bh[np][sub + 2]);
                        MMA16816(acc[mi][nj], ah[mi], bl[np][sub], bl[np][sub + 2]);
                        MMA16816(acc[mi][nj], al[mi], bh[np][sub], bh[np][sub + 2]);
                    }
        }
        __syncthreads();
    }

    #pragma unroll
    for (int mi = 0; mi < 4; mi++)
        #pragma unroll
        for (int nj = 0; nj < 4; nj++) {
            int r = row0 + wm*64 + mi*16 + (lane >> 2);
            int cc = col0 + wn*32 + nj*8 + (lane & 3) * 2;
            *(float2*)(C + (size_t)r * N + cc) =
                make_float2(acc[mi][nj][0], acc[mi][nj][1]);
            *(float2*)(C + (size_t)(r + 8) * N + cc) =
                make_float2(acc[mi][nj][2], acc[mi][nj][3]);
        }
}

// ---------------- fp32 -> bf16 hi/lo split ----------------
__global__ void split_kernel(const float* __restrict__ src,
                             __nv_bfloat16* __restrict__ hi,
                             __nv_bfloat16* __restrict__ lo, int n)
{
    int i = blockIdx.x * blockDim.x + threadIdx.x;
    if (i < n) {
        float v = src[i];
        __nv_bfloat16 h = __float2bfloat16(v);
        hi[i] = h;
        lo[i] = __float2bfloat16(v - __bfloat162float(h));
    }
}

// ---------------- SIMT fp32 GEMM (dt proj): softplus epilogue -------------
__global__ void __launch_bounds__(256, 2) sgemm_softplus(
    const float* __restrict__ A, const float* __restrict__ Bw,
    float* __restrict__ C, const float* __restrict__ bias,
    int M, int N, int K, int lda, int ldb, int ldc)
{
    __shared__ float As[8][128];
    __shared__ float Bs[8][128];
    int tid  = threadIdx.x;
    int row0 = blockIdx.y * 128;
    int col0 = blockIdx.x * 128;
    int tx = tid & 15, ty = tid >> 4;
    int ldRow = tid >> 1, ldCol = (tid & 1) * 4;

    float acc[8][8];
    #pragma unroll
    for (int i = 0; i < 8; i++)
        #pragma unroll
        for (int j = 0; j < 8; j++) acc[i][j] = 0.f;

    const float* Aptr = A + (size_t)(row0 + ldRow) * lda + ldCol;
    bool bValid = (col0 + ldRow) < N;
    const float* Bptr = Bw + (size_t)(col0 + ldRow) * ldb + ldCol;

    for (int k0 = 0; k0 < K; k0 += 8) {
        float4 av = *(const float4*)(Aptr + k0);
        float4 bv = bValid ? *(const float4*)(Bptr + k0) : make_float4(0.f,0.f,0.f,0.f);
        As[ldCol+0][ldRow] = av.x; As[ldCol+1][ldRow] = av.y;
        As[ldCol+2][ldRow] = av.z; As[ldCol+3][ldRow] = av.w;
        Bs[ldCol+0][ldRow] = bv.x; Bs[ldCol+1][ldRow] = bv.y;
        Bs[ldCol+2][ldRow] = bv.z; Bs[ldCol+3][ldRow] = bv.w;
        __syncthreads();
        #pragma unroll
        for (int kk = 0; kk < 8; kk++) {
            float a[8], b[8];
            *(float4*)(a)     = *(const float4*)&As[kk][ty*8];
            *(float4*)(a + 4) = *(const float4*)&As[kk][ty*8+4];
            *(float4*)(b)     = *(const float4*)&Bs[kk][tx*8];
            *(float4*)(b + 4) = *(const float4*)&Bs[kk][tx*8+4];
            #pragma unroll
            for (int i = 0; i < 8; i++)
                #pragma unroll
                for (int j = 0; j < 8; j++)
                    acc[i][j] = fmaf(a[i], b[j], acc[i][j]);
        }
        __syncthreads();
    }
    #pragma unroll
    for (int i = 0; i < 8; i++) {
        int r = row0 + ty*8 + i;
        #pragma unroll
        for (int j = 0; j < 8; j++) {
            int c = col0 + tx*8 + j;
            if (c < N) {
                float v = acc[i][j] + bias[c];
                v = (v > 20.f) ? v : log1pf(__expf(v));
                C[(size_t)r * ldc + c] = v;
            }
        }
    }
}

// ---------------- split-K SIMT GEMM for x_proj ------
__global__ void __launch_bounds__(256, 2) sgemm_splitk(
    const float* __restrict__ A, const float* __restrict__ Bw,
    float* __restrict__ Cpart, int M, int N, int Kc, int lda, int ldb)
{
    __shared__ float As[8][128];
    __shared__ float Bs[8][128];
    int tid  = threadIdx.x;
    int row0 = blockIdx.y * 128;
    int col0 = blockIdx.x * 128;
    int z    = blockIdx.z;
    int tx = tid & 15, ty = tid >> 4;
    int ldRow = tid >> 1, ldCol = (tid & 1) * 4;

    float acc[8][8];
    #pragma unroll
    for (int i = 0; i < 8; i++)
        #pragma unroll
        for (int j = 0; j < 8; j++) acc[i][j] = 0.f;

    const float* Aptr = A + (size_t)(row0 + ldRow) * lda + z * Kc + ldCol;
    bool bValid = (col0 + ldRow) < N;
    const float* Bptr = Bw + (size_t)(col0 + ldRow) * ldb + z * Kc + ldCol;

    for (int k0 = 0; k0 < Kc; k0 += 8) {
        float4 av = *(const float4*)(Aptr + k0);
        float4 bv = bValid ? *(const float4*)(Bptr + k0) : make_float4(0.f,0.f,0.f,0.f);
        As[ldCol+0][ldRow] = av.x; As[ldCol+1][ldRow] = av.y;
        As[ldCol+2][ldRow] = av.z; As[ldCol+3][ldRow] = av.w;
        Bs[ldCol+0][ldRow] = bv.x; Bs[ldCol+1][ldRow] = bv.y;
        Bs[ldCol+2][ldRow] = bv.z; Bs[ldCol+3][ldRow] = bv.w;
        __syncthreads();
        #pragma unroll
        for (int kk = 0; kk < 8; kk++) {
            float a[8], b[8];
            *(float4*)(a)     = *(const float4*)&As[kk][ty*8];
            *(float4*)(a + 4) = *(const float4*)&As[kk][ty*8+4];
            *(float4*)(b)     = *(const float4*)&Bs[kk][tx*8];
            *(float4*)(b + 4) = *(const float4*)&Bs[kk][tx*8+4];
            #pragma unroll
            for (int i = 0; i < 8; i++)
                #pragma unroll
                for (int j = 0; j < 8; j++)
                    acc[i][j] = fmaf(a[i], b[j], acc[i][j]);
        }
        __syncthreads();
    }
    float* Cz = Cpart + (size_t)z * M * N;
    #pragma unroll
    for (int i = 0; i < 8; i++) {
        int r = row0 + ty*8 + i;
        #pragma unroll
        for (int j = 0; j < 8; j++) {
            int c = col0 + tx*8 + j;
            if (c < N) Cz[(size_t)r * N + c] = acc[i][j];
        }
    }
}

// reduce split-K partials; route dt cols to xdbl, B/C cols to transposed arrays
__global__ void reduce_splitk_T(const float* __restrict__ parts)
{
    const int total = MROWS * XDBL_W;
    int i = blockIdx.x * blockDim.x + threadIdx.x;
    if (i >= total) return;
    float v = parts[i] + parts[i + (size_t)total] +
              parts[i + 2*(size_t)total] + parts[i + 3*(size_t)total];
    int m = i / XDBL_W;
    int c = i - m * XDBL_W;
    if (c < DTRANK) {
        g_xdbl[i] = v;
    } else {
        int b = m >> 11, t = m & (SEQ - 1);
        int cc = c - DTRANK;          // 0..31
        if (cc < DSTATE) g_BT[(size_t)(b*DSTATE + cc) * SEQ + t] = v;
        else             g_CT[(size_t)(b*DSTATE + cc - DSTATE) * SEQ + t] = v;
    }
}

// ---------------- causal depthwise conv (k=4) + SiLU ----------------
__global__ void conv_silu_kernel(const float* __restrict__ conv_w,
                                 const float* __restrict__ conv_b)
{
    int idx = blockIdx.x * blockDim.x + threadIdx.x;
    int d = idx & (DINNER - 1);
    int m = idx >> 11;
    int l = m & (SEQ - 1);
    int b = m >> 11;
    float s = conv_b[d];
    #pragma unroll
    for (int j = 0; j < DCONV; j++) {
        int li = l - (DCONV - 1) + j;
        if (li >= 0)
            s = fmaf(conv_w[d * DCONV + j],
                     g_xz[(size_t)(b * SEQ + li) * (2 * DINNER) + d], s);
    }
    g_xc[idx] = s / (1.f + __expf(-s));
}

// ---------------- batched tiled transpose: dt->dtT, xc->xcT, silu(z)->zsT ----
__global__ void __launch_bounds__(256) transpose3_kernel()
{
    __shared__ float tile[32][33];
    int zsel = blockIdx.z;
    int b  = blockIdx.y >> 6;
    int t0 = (blockIdx.y & 63) << 5;
    int d0 = blockIdx.x << 5;
    int tx = threadIdx.x & 31, ty = threadIdx.x >> 5;   // 32 x 8

    const float* src; int stride;
    if (zsel == 0)      { src = g_dt;          stride = DINNER;   }
    else if (zsel == 1) { src = g_xc;          stride = DINNER;   }
    else                { src = g_xz + DINNER; stride = 2*DINNER; }

    #pragma unroll
    for (int k = 0; k < 32; k += 8) {
        float v = src[(size_t)(b*SEQ + t0 + ty + k) * stride + d0 + tx];
        if (zsel == 2) v = v / (1.f + __expf(-v));
        tile[ty + k][tx] = v;
    }
    __syncthreads();
    float* dst = (zsel == 0) ? g_dtT : (zsel == 1) ? g_xcT : g_zsT;
    #pragma unroll
    for (int k = 0; k < 32; k += 8)
        dst[(size_t)(b*DINNER + d0 + ty + k) * SEQ + t0 + tx] = tile[tx][ty + k];
}

// ---------------- selective scan v4: channel-major, reduce-scatter ----------
#define UNR2 16
__global__ void __launch_bounds__(256) scan_kernel(const float* __restrict__ A_log,
                                                   const float* __restrict__ Dp)
{
    int tid  = threadIdx.x;
    int lane = tid & 31;
    int warp = tid >> 5;
    int c2 = lane >> 4;
    int n  = lane & 15;
    int ch = blockIdx.x * 16 + warp * 2 + c2;
    int b  = ch >> 11;
    int d  = ch & (DINNER - 1);

    float Ac = -__expf(__ldg(A_log + d * DSTATE + n));
    float Dd = Dp[d];
    float h  = 0.f;

    const float* dtT = g_dtT + (size_t)ch * SEQ;
    const float* xT  = g_xcT + (size_t)ch * SEQ;
    const float* zT  = g_zsT + (size_t)ch * SEQ;
    const float* BT  = g_BT  + (size_t)(b * DSTATE + n) * SEQ;
    const float* CT  = g_CT  + (size_t)(b * DSTATE + n) * SEQ;
    int srcbase = c2 << 4;

    for (int t0 = 0; t0 < SEQ; t0 += UNR2) {
        float dt_l = __ldg(dtT + t0 + n);
        float x_l  = __ldg(xT  + t0 + n);
        float z_l  = __ldg(zT  + t0 + n);
        float pre_l = dt_l * x_l;

        float Bn[UNR2], Cn[UNR2];
        #pragma unroll
        for (int q = 0; q < UNR2; q += 4) {
            float4 bq = *(const float4*)(BT + t0 + q);
            float4 cq = *(const float4*)(CT + t0 + q);
            Bn[q] = bq.x; Bn[q+1] = bq.y; Bn[q+2] = bq.z; Bn[q+3] = bq.w;
            Cn[q] = cq.x; Cn[q+1] = cq.y; Cn[q+2] = cq.z; Cn[q+3] = cq.w;
        }

        // broadcast dt and dt*x per timestep
        float dA[UNR2];
        #pragma unroll
        for (int u = 0; u < UNR2; u++) {
            float dtu  = __shfl_sync(0xffffffffu, dt_l,  srcbase + u);
            float preu = __shfl_sync(0xffffffffu, pre_l, srcbase + u);
            Bn[u] = preu * Bn[u];              // dt * x * B_n  (dBx)
            dA[u] = __expf(dtu * Ac);
        }

        // serial recurrence + C projection
        float p[UNR2];
        #pragma unroll
        for (int u = 0; u < UNR2; u++) {
            h = fmaf(dA[u], h, Bn[u]);
            p[u] = h * Cn[u];
        }

        // reduce-scatter: 16 cross-lane sums in 15 shfl; lane n ends with sum
        // for timestep t0+n.
        float q8[8];
        #pragma unroll
        for (int v = 0; v < 8; v++) {
            float keep = (n & 8) ? p[v + 8] : p[v];
            float send = (n & 8) ? p[v]     : p[v + 8];
            q8[v] = keep + __shfl_xor_sync(0xffffffffu, send, 8);
        }
        float q4[4];
        #pragma unroll
        for (int v = 0; v < 4; v++) {
            float keep = (n & 4) ? q8[v + 4] : q8[v];
            float send = (n & 4) ? q8[v]     : q8[v + 4];
            q4[v] = keep + __shfl_xor_sync(0xffffffffu, send, 4);
        }
        float q2[2];
        #pragma unroll
        for (int v = 0; v < 2; v++) {
            float keep = (n & 2) ? q4[v + 2] : q4[v];
            float send = (n & 2) ? q4[v]     : q4[v + 2];
            q2[v] = keep + __shfl_xor_sync(0xffffffffu, send, 2);
        }
        float keep = (n & 1) ? q2[1] : q2[0];
        float send = (n & 1) ? q2[0] : q2[1];
        float ps = keep + __shfl_xor_sync(0xffffffffu, send, 1);

        float yv = fmaf(Dd, x_l, ps) * z_l;    // x_l = x[t0+n], z_l = silu(z)[t0+n]
        __nv_bfloat16 hh = __float2bfloat16(yv);
        size_t oy = (size_t)(b * SEQ + t0 + n) * DINNER + d;
        g_yh[oy] = hh;
        g_yl[oy] = __float2bfloat16(yv - __bfloat162float(hh));
    }
}

// ---------------- launch ----------------
extern "C" void kernel_launch(void* const* d_in, const int* in_sizes, int n_in,
                              void* d_out, int out_size)
{
    const float* x          = (const float*)d_in[0];
    const float* in_proj_w  = (const float*)d_in[1];
    const float* conv_w     = (const float*)d_in[2];
    const float* conv_b     = (const float*)d_in[3];
    const float* A_log      = (const float*)d_in[4];
    const float* Dp         = (const float*)d_in[5];
    const float* x_proj_w   = (const float*)d_in[6];
    const float* dt_proj_w  = (const float*)d_in[7];
    const float* dt_proj_b  = (const float*)d_in[8];
    const float* out_proj_w = (const float*)d_in[9];
    float*       out        = (float*)d_out;

    float *xz, *xc, *xdbl, *xdblp, *dt;
    __nv_bfloat16 *xh, *xl, *wih, *wil, *yh, *yl, *woh, *wol;
    cudaGetSymbolAddress((void**)&xz,    g_xz);
    cudaGetSymbolAddress((void**)&xc,    g_xc);
    cudaGetSymbolAddress((void**)&xdbl,  g_xdbl);
    cudaGetSymbolAddress((void**)&xdblp, g_xdblp);
    cudaGetSymbolAddress((void**)&dt,    g_dt);
    cudaGetSymbolAddress((void**)&xh,  g_xh);
    cudaGetSymbolAddress((void**)&xl,  g_xl);
    cudaGetSymbolAddress((void**)&wih, g_wih);
    cudaGetSymbolAddress((void**)&wil, g_wil);
    cudaGetSymbolAddress((void**)&yh,  g_yh);
    cudaGetSymbolAddress((void**)&yl,  g_yl);
    cudaGetSymbolAddress((void**)&woh, g_woh);
    cudaGetSymbolAddress((void**)&wol, g_wol);

    cudaFuncSetAttribute(hmma_gemm, cudaFuncAttributeMaxDynamicSharedMemorySize,
                         HMMA_SMEM);

    // 0) bf16 hi/lo splits
    split_kernel<<<(MROWS*DMODEL + 255)/256, 256>>>(x, xh, xl, MROWS*DMODEL);
    split_kernel<<<(2*DINNER*DMODEL + 255)/256, 256>>>(in_proj_w, wih, wil, 2*DINNER*DMODEL);
    split_kernel<<<(DMODEL*DINNER + 255)/256, 256>>>(out_proj_w, woh, wol, DMODEL*DINNER);

    // 1) xz = x @ in_proj_w^T
    hmma_gemm<<<dim3(32, 32), 256, HMMA_SMEM>>>(xh, xl, wih, wil, xz, DMODEL, 2*DINNER);

    // 2) causal depthwise conv + silu
    conv_silu_kernel<<<(MROWS * DINNER) / 256, 256>>>(conv_w, conv_b);

    // 3) x_dbl = xc @ x_proj_w^T  — split-K x4 + routed reduce (B,C transposed)
    sgemm_splitk<<<dim3(1, 32, KSPLIT), 256>>>(xc, x_proj_w, xdblp,
                                               MROWS, XDBL_W, DINNER/KSPLIT,
                                               DINNER, DINNER);
    reduce_splitk_T<<<(MROWS*XDBL_W + 255)/256, 256>>>(xdblp);

    // 4) dt = softplus(x_dbl[:, :64] @ dt_proj_w^T + b)
    sgemm_softplus<<<dim3(16, 32), 256>>>(xdbl, dt_proj_w, dt, dt_proj_b,
                                          MROWS, DINNER, DTRANK,
                                          XDBL_W, DTRANK, DINNER);

    // 4b) transposes: dt->dtT, xc->xcT, silu(z)->zsT
    transpose3_kernel<<<dim3(64, 128, 3), 256>>>();

    // 5) selective scan v4
    scan_kernel<<<256, 256>>>(A_log, Dp);

    // 6) out = y @ out_proj_w^T
    hmma_gemm<<<dim3(8, 32), 256, HMMA_SMEM>>>(yh, yl, woh, wol, out, DINNER, DMODEL);
}

// round 7
// speedup vs baseline: 3.9553x; 1.1901x over previous
#include <cuda_runtime.h>
#include <cuda_bf16.h>
#include <math.h>
#include <stdint.h>

#define B_SZ   2
#define SEQ    2048
#define DMODEL 1024
#define DINNER 2048
#define DSTATE 16
#define DTRANK 64
#define DCONV  4
#define MROWS  (B_SZ*SEQ)   // 4096
#define XDBL_W 96
#define KSPLIT 4

// ---------------- scratch ----------------
__device__ float g_xz   [(size_t)MROWS * 2 * DINNER];
__device__ float g_xc   [(size_t)MROWS * DINNER];
__device__ float g_xdbl [(size_t)MROWS * XDBL_W];
__device__ float g_xdblp[(size_t)KSPLIT * MROWS * XDBL_W];
__device__ float g_dt   [(size_t)MROWS * DINNER];

// channel-major transposed arrays for the scan
__device__ float g_dtT  [(size_t)MROWS * DINNER];
__device__ float g_xcT  [(size_t)MROWS * DINNER];
__device__ float g_zsT  [(size_t)MROWS * DINNER];
__device__ float g_BT   [(size_t)B_SZ * DSTATE * SEQ];
__device__ float g_CT   [(size_t)B_SZ * DSTATE * SEQ];

// bf16 hi/lo splits
__device__ __nv_bfloat16 g_xh [(size_t)MROWS * DMODEL];
__device__ __nv_bfloat16 g_xl [(size_t)MROWS * DMODEL];
__device__ __nv_bfloat16 g_wih[(size_t)(2*DINNER) * DMODEL];
__device__ __nv_bfloat16 g_wil[(size_t)(2*DINNER) * DMODEL];
__device__ __nv_bfloat16 g_yh [(size_t)MROWS * DINNER];
__device__ __nv_bfloat16 g_yl [(size_t)MROWS * DINNER];
__device__ __nv_bfloat16 g_woh[(size_t)DMODEL * DINNER];
__device__ __nv_bfloat16 g_wol[(size_t)DMODEL * DINNER];

// ======================= helpers =======================
__device__ __forceinline__ uint32_t smem_to_u32(const void* p) {
    uint32_t a;
    asm("{ .reg .u64 t; cvta.to.shared.u64 t, %1; cvt.u32.u64 %0, t; }"
        : "=r"(a) : "l"(p));
    return a;
}

#define LDM_X4(r, addr) \
    asm volatile("ldmatrix.sync.aligned.m8n8.x4.shared.b16 {%0,%1,%2,%3}, [%4];" \
        : "=r"((r)[0]), "=r"((r)[1]), "=r"((r)[2]), "=r"((r)[3]) : "r"(addr))

#define MMA16816(c, a, b0, b1) \
    asm volatile("mma.sync.aligned.m16n8k16.row.col.f32.bf16.bf16.f32 " \
        "{%0,%1,%2,%3}, {%4,%5,%6,%7}, {%8,%9}, {%0,%1,%2,%3};" \
        : "+f"((c)[0]), "+f"((c)[1]), "+f"((c)[2]), "+f"((c)[3]) \
        : "r"((a)[0]), "r"((a)[1]), "r"((a)[2]), "r"((a)[3]), "r"(b0), "r"(b1))

#define CP_ASYNC16(saddr, gptr) \
    asm volatile("cp.async.cg.shared.global [%0], [%1], 16;" \
        :: "r"(saddr), "l"(gptr) : "memory")
#define CP_COMMIT() asm volatile("cp.async.commit_group;" ::: "memory")
#define CP_WAIT(n)  asm volatile("cp.async.wait_group %0;" :: "n"(n) : "memory")

// ================= split-bf16 HMMA GEMM, 2-stage =================
#define LDSH   40
#define STG_H  (128*LDSH)
#define STAGE_H (4*STG_H)
#define HMMA_SMEM (2*STAGE_H*2)      // 81920 bytes -> 2 CTAs/SM

__global__ void __launch_bounds__(256, 1)
hmma_gemm(const __nv_bfloat16* __restrict__ Ah, const __nv_bfloat16* __restrict__ Al,
          const __nv_bfloat16* __restrict__ Bh, const __nv_bfloat16* __restrict__ Bl,
          float* __restrict__ C, int K, int N)
{
    extern __shared__ __nv_bfloat16 sm[];
    const int tid  = threadIdx.x;
    const int lane = tid & 31;
    const int w    = tid >> 5;
    const int wm   = w >> 2;
    const int wn   = w & 3;
    const int row0 = blockIdx.y * 128;
    const int col0 = blockIdx.x * 128;
    const uint32_t sbase = smem_to_u32(sm);

    const int nc = K >> 5;

    auto load_stage = [&](int c, int s) {
        #pragma unroll
        for (int j = 0; j < 2; j++) {
            int i = tid + j * 256;
            int r = i >> 2, q = i & 3;
            size_t gA = (size_t)(row0 + r) * K + c * 32 + q * 8;
            size_t gB = (size_t)(col0 + r) * K + c * 32 + q * 8;
            uint32_t so = (uint32_t)(s * STAGE_H + r * LDSH + q * 8);
            uint32_t sa = sbase + so * 2;
            CP_ASYNC16(sa,                (const void*)(Ah + gA));
            CP_ASYNC16(sa + STG_H*2,      (const void*)(Al + gA));
            CP_ASYNC16(sa + 2*STG_H*2,    (const void*)(Bh + gB));
            CP_ASYNC16(sa + 3*STG_H*2,    (const void*)(Bl + gB));
        }
    };

    float acc[4][4][4];
    #pragma unroll
    for (int mi = 0; mi < 4; mi++)
        #pragma unroll
        for (int nj = 0; nj < 4; nj++)
            #pragma unroll
            for (int q = 0; q < 4; q++) acc[mi][nj][q] = 0.f;

    load_stage(0, 0);
    CP_COMMIT();

    for (int c = 0; c < nc; c++) {
        int s = c & 1;
        if (c + 1 < nc) {
            load_stage(c + 1, (c + 1) & 1);
            CP_COMMIT();
            CP_WAIT(1);
        } else {
            CP_WAIT(0);
        }
        __syncthreads();

        #pragma unroll
        for (int ks = 0; ks < 2; ks++) {
            uint32_t ah[4][4], al[4][4];
            #pragma unroll
            for (int mi = 0; mi < 4; mi++) {
                uint32_t off = (uint32_t)(s * STAGE_H
                             + (wm*64 + mi*16 + (lane & 15)) * LDSH
                             + ks*16 + (lane >> 4) * 8);
                uint32_t ad = sbase + off * 2;
                LDM_X4(ah[mi], ad);
                LDM_X4(al[mi], ad + STG_H*2);
            }
            uint32_t bh[2][4], bl[2][4];
            #pragma unroll
            for (int np = 0; np < 2; np++) {
                uint32_t off = (uint32_t)(s * STAGE_H + 2*STG_H
                             + (wn*32 + np*16 + (lane & 7) + ((lane >> 3) & 1) * 8) * LDSH
                             + ks*16 + (lane >> 4) * 8);
                uint32_t bd = sbase + off * 2;
                LDM_X4(bh[np], bd);
                LDM_X4(bl[np], bd + STG_H*2);
            }
            #pragma unroll
            for (int mi = 0; mi < 4; mi++)
                #pragma unroll
                for (int np = 0; np < 2; np++)
                    #pragma unroll
                    for (int sub = 0; sub < 2; sub++) {
                        int nj = np * 2 + sub;
                        MMA16816(acc[mi][nj], ah[mi], bh[np][sub], bh[np][sub + 2]);
                        MMA16816(acc[mi][nj], ah[mi], bl[np][sub], bl[np][sub + 2]);
                        MMA16816(acc[mi][nj], al[mi], bh[np][sub], bh[np][sub + 2]);
                    }
        }
        __syncthreads();
    }

    #pragma unroll
    for (int mi = 0; mi < 4; mi++)
        #pragma unroll
        for (int nj = 0; nj < 4; nj++) {
            int r = row0 + wm*64 + mi*16 + (lane >> 2);
            int cc = col0 + wn*32 + nj*8 + (lane & 3) * 2;
            *(float2*)(C + (size_t)r * N + cc) =
                make_float2(acc[mi][nj][0], acc[mi][nj][1]);
            *(float2*)(C + (size_t)(r + 8) * N + cc) =
                make_float2(acc[mi][nj][2], acc[mi][nj][3]);
        }
}

// ---------------- fp32 -> bf16 hi/lo split ----------------
__global__ void split_kernel(const float* __restrict__ src,
                             __nv_bfloat16* __restrict__ hi,
                             __nv_bfloat16* __restrict__ lo, int n)
{
    int i = blockIdx.x * blockDim.x + threadIdx.x;
    if (i < n) {
        float v = src[i];
        __nv_bfloat16 h = __float2bfloat16(v);
        hi[i] = h;
        lo[i] = __float2bfloat16(v - __bfloat162float(h));
    }
}

// ---------------- SIMT fp32 GEMM (dt proj): softplus epilogue -------------
__global__ void __launch_bounds__(256, 2) sgemm_softplus(
    const float* __restrict__ A, const float* __restrict__ Bw,
    float* __restrict__ C, const float* __restrict__ bias,
    int M, int N, int K, int lda, int ldb, int ldc)
{
    __shared__ float As[8][128];
    __shared__ float Bs[8][128];
    int tid  = threadIdx.x;
    int row0 = blockIdx.y * 128;
    int col0 = blockIdx.x * 128;
    int tx = tid & 15, ty = tid >> 4;
    int ldRow = tid >> 1, ldCol = (tid & 1) * 4;

    float acc[8][8];
    #pragma unroll
    for (int i = 0; i < 8; i++)
        #pragma unroll
        for (int j = 0; j < 8; j++) acc[i][j] = 0.f;

    const float* Aptr = A + (size_t)(row0 + ldRow) * lda + ldCol;
    bool bValid = (col0 + ldRow) < N;
    const float* Bptr = Bw + (size_t)(col0 + ldRow) * ldb + ldCol;

    for (int k0 = 0; k0 < K; k0 += 8) {
        float4 av = *(const float4*)(Aptr + k0);
        float4 bv = bValid ? *(const float4*)(Bptr + k0) : make_float4(0.f,0.f,0.f,0.f);
        As[ldCol+0][ldRow] = av.x; As[ldCol+1][ldRow] = av.y;
        As[ldCol+2][ldRow] = av.z; As[ldCol+3][ldRow] = av.w;
        Bs[ldCol+0][ldRow] = bv.x; Bs[ldCol+1][ldRow] = bv.y;
        Bs[ldCol+2][ldRow] = bv.z; Bs[ldCol+3][ldRow] = bv.w;
        __syncthreads();
        #pragma unroll
        for (int kk = 0; kk < 8; kk++) {
            float a[8], b[8];
            *(float4*)(a)     = *(const float4*)&As[kk][ty*8];
            *(float4*)(a + 4) = *(const float4*)&As[kk][ty*8+4];
            *(float4*)(b)     = *(const float4*)&Bs[kk][tx*8];
            *(float4*)(b + 4) = *(const float4*)&Bs[kk][tx*8+4];
            #pragma unroll
            for (int i = 0; i < 8; i++)
                #pragma unroll
                for (int j = 0; j < 8; j++)
                    acc[i][j] = fmaf(a[i], b[j], acc[i][j]);
        }
        __syncthreads();
    }
    #pragma unroll
    for (int i = 0; i < 8; i++) {
        int r = row0 + ty*8 + i;
        #pragma unroll
        for (int j = 0; j < 8; j++) {
            int c = col0 + tx*8 + j;
            if (c < N) {
                float v = acc[i][j] + bias[c];
                v = (v > 20.f) ? v : log1pf(__expf(v));
                C[(size_t)r * ldc + c] = v;
            }
        }
    }
}

// ---------------- split-K SIMT GEMM for x_proj ------
__global__ void __launch_bounds__(256, 2) sgemm_splitk(
    const float* __restrict__ A, const float* __restrict__ Bw,
    float* __restrict__ Cpart, int M, int N, int Kc, int lda, int ldb)
{
    __shared__ float As[8][128];
    __shared__ float Bs[8][128];
    int tid  = threadIdx.x;
    int row0 = blockIdx.y * 128;
    int col0 = blockIdx.x * 128;
    int z    = blockIdx.z;
    int tx = tid & 15, ty = tid >> 4;
    int ldRow = tid >> 1, ldCol = (tid & 1) * 4;

    float acc[8][8];
    #pragma unroll
    for (int i = 0; i < 8; i++)
        #pragma unroll
        for (int j = 0; j < 8; j++) acc[i][j] = 0.f;

    const float* Aptr = A + (size_t)(row0 + ldRow) * lda + z * Kc + ldCol;
    bool bValid = (col0 + ldRow) < N;
    const float* Bptr = Bw + (size_t)(col0 + ldRow) * ldb + z * Kc + ldCol;

    for (int k0 = 0; k0 < Kc; k0 += 8) {
        float4 av = *(const float4*)(Aptr + k0);
        float4 bv = bValid ? *(const float4*)(Bptr + k0) : make_float4(0.f,0.f,0.f,0.f);
        As[ldCol+0][ldRow] = av.x; As[ldCol+1][ldRow] = av.y;
        As[ldCol+2][ldRow] = av.z; As[ldCol+3][ldRow] = av.w;
        Bs[ldCol+0][ldRow] = bv.x; Bs[ldCol+1][ldRow] = bv.y;
        Bs[ldCol+2][ldRow] = bv.z; Bs[ldCol+3][ldRow] = bv.w;
        __syncthreads();
        #pragma unroll
        for (int kk = 0; kk < 8; kk++) {
            float a[8], b[8];
            *(float4*)(a)     = *(const float4*)&As[kk][ty*8];
            *(float4*)(a + 4) = *(const float4*)&As[kk][ty*8+4];
            *(float4*)(b)     = *(const float4*)&Bs[kk][tx*8];
            *(float4*)(b + 4) = *(const float4*)&Bs[kk][tx*8+4];
            #pragma unroll
            for (int i = 0; i < 8; i++)
                #pragma unroll
                for (int j = 0; j < 8; j++)
                    acc[i][j] = fmaf(a[i], b[j], acc[i][j]);
        }
        __syncthreads();
    }
    float* Cz = Cpart + (size_t)z * M * N;
    #pragma unroll
    for (int i = 0; i < 8; i++) {
        int r = row0 + ty*8 + i;
        #pragma unroll
        for (int j = 0; j < 8; j++) {
            int c = col0 + tx*8 + j;
            if (c < N) Cz[(size_t)r * N + c] = acc[i][j];
        }
    }
}

// reduce split-K partials; route dt cols to xdbl, B/C cols to transposed arrays
__global__ void reduce_splitk_T(const float* __restrict__ parts)
{
    const int total = MROWS * XDBL_W;
    int i = blockIdx.x * blockDim.x + threadIdx.x;
    if (i >= total) return;
    float v = parts[i] + parts[i + (size_t)total] +
              parts[i + 2*(size_t)total] + parts[i + 3*(size_t)total];
    int m = i / XDBL_W;
    int c = i - m * XDBL_W;
    if (c < DTRANK) {
        g_xdbl[i] = v;
    } else {
        int b = m >> 11, t = m & (SEQ - 1);
        int cc = c - DTRANK;          // 0..31
        if (cc < DSTATE) g_BT[(size_t)(b*DSTATE + cc) * SEQ + t] = v;
        else             g_CT[(size_t)(b*DSTATE + cc - DSTATE) * SEQ + t] = v;
    }
}

// ---------------- causal depthwise conv (k=4) + SiLU ----------------
__global__ void conv_silu_kernel(const float* __restrict__ conv_w,
                                 const float* __restrict__ conv_b)
{
    int idx = blockIdx.x * blockDim.x + threadIdx.x;
    int d = idx & (DINNER - 1);
    int m = idx >> 11;
    int l = m & (SEQ - 1);
    int b = m >> 11;
    float s = conv_b[d];
    #pragma unroll
    for (int j = 0; j < DCONV; j++) {
        int li = l - (DCONV - 1) + j;
        if (li >= 0)
            s = fmaf(conv_w[d * DCONV + j],
                     g_xz[(size_t)(b * SEQ + li) * (2 * DINNER) + d], s);
    }
    g_xc[idx] = s / (1.f + __expf(-s));
}

// ---------------- batched tiled transpose: dt->dtT, xc->xcT, silu(z)->zsT ----
__global__ void __launch_bounds__(256) transpose3_kernel()
{
    __shared__ float tile[32][33];
    int zsel = blockIdx.z;
    int b  = blockIdx.y >> 6;
    int t0 = (blockIdx.y & 63) << 5;
    int d0 = blockIdx.x << 5;
    int tx = threadIdx.x & 31, ty = threadIdx.x >> 5;   // 32 x 8

    const float* src; int stride;
    if (zsel == 0)      { src = g_dt;          stride = DINNER;   }
    else if (zsel == 1) { src = g_xc;          stride = DINNER;   }
    else                { src = g_xz + DINNER; stride = 2*DINNER; }

    #pragma unroll
    for (int k = 0; k < 32; k += 8) {
        float v = src[(size_t)(b*SEQ + t0 + ty + k) * stride + d0 + tx];
        if (zsel == 2) v = v / (1.f + __expf(-v));
        tile[ty + k][tx] = v;
    }
    __syncthreads();
    float* dst = (zsel == 0) ? g_dtT : (zsel == 1) ? g_xcT : g_zsT;
    #pragma unroll
    for (int k = 0; k < 32; k += 8)
        dst[(size_t)(b*DINNER + d0 + ty + k) * SEQ + t0 + tx] = tile[tx][ty + k];
}

// ---------------- selective scan v5: smem B/C tiles, packed stores ----------
#define UNR2 16
#define T_TILE 128
#define SPAD 132     // 132 mod 32 = 4 -> conflict-free 8-lane phases for LDS.128
__global__ void __launch_bounds__(256) scan_kernel(const float* __restrict__ A_log,
                                                   const float* __restrict__ Dp)
{
    __shared__ float sB[DSTATE][SPAD];
    __shared__ float sC[DSTATE][SPAD];

    int tid  = threadIdx.x;
    int lane = tid & 31;
    int warp = tid >> 5;
    int c2 = lane >> 4;
    int n  = lane & 15;
    int ch = blockIdx.x * 16 + warp * 2 + c2;
    int b  = ch >> 11;
    int d  = ch & (DINNER - 1);
    int d0 = d & ~1;                // even channel of the pair

    float Ac = -__expf(__ldg(A_log + d * DSTATE + n));
    float Dd = Dp[d];
    float h  = 0.f;

    const float* dtT = g_dtT + (size_t)ch * SEQ;
    const float* xT  = g_xcT + (size_t)ch * SEQ;
    const float* zT  = g_zsT + (size_t)ch * SEQ;
    const float* BTb = g_BT  + (size_t)b * DSTATE * SEQ;
    const float* CTb = g_CT  + (size_t)b * DSTATE * SEQ;
    int srcbase = c2 << 4;

    int ldr = tid >> 5;             // 0..7
    int ldc = (tid & 31) * 4;       // 0..124

    for (int tb = 0; tb < SEQ; tb += T_TILE) {
        __syncthreads();            // prev tile fully consumed
        #pragma unroll
        for (int rr = 0; rr < 2; rr++) {
            int r = ldr + rr * 8;
            float4 bv = *(const float4*)(BTb + (size_t)r * SEQ + tb + ldc);
            float4 cv = *(const float4*)(CTb + (size_t)r * SEQ + tb + ldc);
            *(float4*)&sB[r][ldc] = bv;
            *(float4*)&sC[r][ldc] = cv;
        }
        __syncthreads();

        for (int tt = 0; tt < T_TILE; tt += UNR2) {
            int t0 = tb + tt;
            float dt_l = __ldg(dtT + t0 + n);
            float x_l  = __ldg(xT  + t0 + n);
            float z_l  = __ldg(zT  + t0 + n);
            float pre_l = dt_l * x_l;

            float Bn[UNR2], Cn[UNR2];
            #pragma unroll
            for (int q = 0; q < UNR2; q += 4) {
                float4 bq = *(const float4*)&sB[n][tt + q];
                float4 cq = *(const float4*)&sC[n][tt + q];
                Bn[q] = bq.x; Bn[q+1] = bq.y; Bn[q+2] = bq.z; Bn[q+3] = bq.w;
                Cn[q] = cq.x; Cn[q+1] = cq.y; Cn[q+2] = cq.z; Cn[q+3] = cq.w;
            }

            float dA[UNR2];
            #pragma unroll
            for (int u = 0; u < UNR2; u++) {
                float dtu  = __shfl_sync(0xffffffffu, dt_l,  srcbase + u);
                float preu = __shfl_sync(0xffffffffu, pre_l, srcbase + u);
                Bn[u] = preu * Bn[u];
                dA[u] = __expf(dtu * Ac);
            }

            float p[UNR2];
            #pragma unroll
            for (int u = 0; u < UNR2; u++) {
                h = fmaf(dA[u], h, Bn[u]);
                p[u] = h * Cn[u];
            }

            // reduce-scatter: lane n ends with sum for timestep t0+n
            float q8[8];
            #pragma unroll
            for (int v = 0; v < 8; v++) {
                float keep = (n & 8) ? p[v + 8] : p[v];
                float send = (n & 8) ? p[v]     : p[v + 8];
                q8[v] = keep + __shfl_xor_sync(0xffffffffu, send, 8);
            }
            float q4[4];
            #pragma unroll
            for (int v = 0; v < 4; v++) {
                float keep = (n & 4) ? q8[v + 4] : q8[v];
                float send = (n & 4) ? q8[v]     : q8[v + 4];
                q4[v] = keep + __shfl_xor_sync(0xffffffffu, send, 4);
            }
            float q2[2];
            #pragma unroll
            for (int v = 0; v < 2; v++) {
                float keep = (n & 2) ? q2[0]*0.f + ((n & 2) ? q4[v + 2] : q4[v]) : q4[v];
                keep = (n & 2) ? q4[v + 2] : q4[v];
                float send = (n & 2) ? q4[v]     : q4[v + 2];
                q2[v] = keep + __shfl_xor_sync(0xffffffffu, send, 2);
            }
            float keep = (n & 1) ? q2[1] : q2[0];
            float send = (n & 1) ? q2[0] : q2[1];
            float ps = keep + __shfl_xor_sync(0xffffffffu, send, 1);

            float yv = fmaf(Dd, x_l, ps) * z_l;
            // grab partner half-warp's value (other channel of the pair)
            float yvp = __shfl_xor_sync(0xffffffffu, yv, 16);
            if (c2 == 0) {
                __nv_bfloat16 h0 = __float2bfloat16(yv);
                __nv_bfloat16 h1 = __float2bfloat16(yvp);
                __nv_bfloat16 l0 = __float2bfloat16(yv  - __bfloat162float(h0));
                __nv_bfloat16 l1 = __float2bfloat16(yvp - __bfloat162float(h1));
                size_t m = (size_t)(b * SEQ + t0 + n);
                *(__nv_bfloat162*)(g_yh + m * DINNER + d0) = __halves2bfloat162(h0, h1);
                *(__nv_bfloat162*)(g_yl + m * DINNER + d0) = __halves2bfloat162(l0, l1);
            }
        }
    }
}

// ---------------- launch ----------------
extern "C" void kernel_launch(void* const* d_in, const int* in_sizes, int n_in,
                              void* d_out, int out_size)
{
    const float* x          = (const float*)d_in[0];
    const float* in_proj_w  = (const float*)d_in[1];
    const float* conv_w     = (const float*)d_in[2];
    const float* conv_b     = (const float*)d_in[3];
    const float* A_log      = (const float*)d_in[4];
    const float* Dp         = (const float*)d_in[5];
    const float* x_proj_w   = (const float*)d_in[6];
    const float* dt_proj_w  = (const float*)d_in[7];
    const float* dt_proj_b  = (const float*)d_in[8];
    const float* out_proj_w = (const float*)d_in[9];
    float*       out        = (float*)d_out;

    float *xz, *xc, *xdbl, *xdblp, *dt;
    __nv_bfloat16 *xh, *xl, *wih, *wil, *yh, *yl, *woh, *wol;
    cudaGetSymbolAddress((void**)&xz,    g_xz);
    cudaGetSymbolAddress((void**)&xc,    g_xc);
    cudaGetSymbolAddress((void**)&xdbl,  g_xdbl);
    cudaGetSymbolAddress((void**)&xdblp, g_xdblp);
    cudaGetSymbolAddress((void**)&dt,    g_dt);
    cudaGetSymbolAddress((void**)&xh,  g_xh);
    cudaGetSymbolAddress((void**)&xl,  g_xl);
    cudaGetSymbolAddress((void**)&wih, g_wih);
    cudaGetSymbolAddress((void**)&wil, g_wil);
    cudaGetSymbolAddress((void**)&yh,  g_yh);
    cudaGetSymbolAddress((void**)&yl,  g_yl);
    cudaGetSymbolAddress((void**)&woh, g_woh);
    cudaGetSymbolAddress((void**)&wol, g_wol);

    cudaFuncSetAttribute(hmma_gemm, cudaFuncAttributeMaxDynamicSharedMemorySize,
                         HMMA_SMEM);

    // 0) bf16 hi/lo splits
    split_kernel<<<(MROWS*DMODEL + 255)/256, 256>>>(x, xh, xl, MROWS*DMODEL);
    split_kernel<<<(2*DINNER*DMODEL + 255)/256, 256>>>(in_proj_w, wih, wil, 2*DINNER*DMODEL);
    split_kernel<<<(DMODEL*DINNER + 255)/256, 256>>>(out_proj_w, woh, wol, DMODEL*DINNER);

    // 1) xz = x @ in_proj_w^T
    hmma_gemm<<<dim3(32, 32), 256, HMMA_SMEM>>>(xh, xl, wih, wil, xz, DMODEL, 2*DINNER);

    // 2) causal depthwise conv + silu
    conv_silu_kernel<<<(MROWS * DINNER) / 256, 256>>>(conv_w, conv_b);

    // 3) x_dbl = xc @ x_proj_w^T  — split-K x4 + routed reduce (B,C transposed)
    sgemm_splitk<<<dim3(1, 32, KSPLIT), 256>>>(xc, x_proj_w, xdblp,
                                               MROWS, XDBL_W, DINNER/KSPLIT,
                                               DINNER, DINNER);
    reduce_splitk_T<<<(MROWS*XDBL_W + 255)/256, 256>>>(xdblp);

    // 4) dt = softplus(x_dbl[:, :64] @ dt_proj_w^T + b)
    sgemm_softplus<<<dim3(16, 32), 256>>>(xdbl, dt_proj_w, dt, dt_proj_b,
                                          MROWS, DINNER, DTRANK,
                                          XDBL_W, DTRANK, DINNER);

    // 4b) transposes: dt->dtT, xc->xcT, silu(z)->zsT
    transpose3_kernel<<<dim3(64, 128, 3), 256>>>();

    // 5) selective scan v5
    scan_kernel<<<256, 256>>>(A_log, Dp);

    // 6) out = y @ out_proj_w^T
    hmma_gemm<<<dim3(8, 32), 256, HMMA_SMEM>>>(yh, yl, woh, wol, out, DINNER, DMODEL);
}